// round 1
// baseline (speedup 1.0000x reference)
#include <cuda_runtime.h>
#include <math.h>

// ---------------------------------------------------------------------------
// DecoderLayerWithContext: pre-LN causal self-attn + cross-attn + GELU FFN
// B=2, T=S=2048, E=1024, H=16, D=64, fp32.
// Round 1: correct fp32 SIMT baseline. All GEMMs via 128x128x8 tiled SGEMM
// (8x8 microtile). Scores materialized in device-global scratch; causal
// blocks skipped. Epilogues (bias/residual/GELU) fused into GEMMs.
// ---------------------------------------------------------------------------

namespace cfg {
constexpr int E  = 1024;
constexpr int NH = 16;
constexpr int HD = 64;
constexpr int B  = 2;
constexpr int T  = 2048;
constexpr int S  = 2048;
constexpr int BH = B * NH;
constexpr float SCALE = 0.03125f;  // 1/sqrt(E) = 1/32
}

// Scratch (device globals: allocation-free per harness rules)
__device__ float g_h  [cfg::B * cfg::T * cfg::E];
__device__ float g_q  [cfg::B * cfg::T * cfg::E];
__device__ float g_k  [cfg::B * cfg::S * cfg::E];
__device__ float g_v  [cfg::B * cfg::S * cfg::E];
__device__ float g_a  [cfg::B * cfg::T * cfg::E];
__device__ float g_x1 [cfg::B * cfg::T * cfg::E];
__device__ float g_x2 [cfg::B * cfg::T * cfg::E];
__device__ float g_ffn[(size_t)cfg::B * cfg::T * 4 * cfg::E];
__device__ float g_sc [(size_t)cfg::BH * cfg::T * cfg::S];

// ---------------------------------------------------------------------------
// LayerNorm: one block per row of E=1024, 256 threads, float4 per thread.
// ---------------------------------------------------------------------------
__global__ void ln_kernel(const float* __restrict__ X, const float* __restrict__ gam,
                          const float* __restrict__ bet, float* __restrict__ Y) {
    __shared__ float red[256];
    const int row = blockIdx.x;
    const int tid = threadIdx.x;
    const float4 v = ((const float4*)(X + (size_t)row * cfg::E))[tid];

    float s = v.x + v.y + v.z + v.w;
    red[tid] = s; __syncthreads();
    for (int off = 128; off; off >>= 1) {
        if (tid < off) red[tid] += red[tid + off];
        __syncthreads();
    }
    const float mu = red[0] * (1.0f / cfg::E);
    __syncthreads();

    const float dx = v.x - mu, dy = v.y - mu, dz = v.z - mu, dw = v.w - mu;
    red[tid] = dx*dx + dy*dy + dz*dz + dw*dw; __syncthreads();
    for (int off = 128; off; off >>= 1) {
        if (tid < off) red[tid] += red[tid + off];
        __syncthreads();
    }
    const float var = red[0] * (1.0f / cfg::E);
    const float r = rsqrtf(var + 1e-5f);

    const float4 g4 = ((const float4*)gam)[tid];
    const float4 b4 = ((const float4*)bet)[tid];
    float4 o;
    o.x = dx * r * g4.x + b4.x;
    o.y = dy * r * g4.y + b4.y;
    o.z = dz * r * g4.z + b4.z;
    o.w = dw * r * g4.w + b4.w;
    ((float4*)(Y + (size_t)row * cfg::E))[tid] = o;
}

// ---------------------------------------------------------------------------
// SGEMM NN: C[M,N] = epi(A[M,K] @ B[K,N] + bias) + res
// 128x128 tile, BK=8, 256 threads, 8x8 microtile.
// Requires M%128==0, N%128==0, K%8==0 (always true for these shapes).
// ---------------------------------------------------------------------------
__global__ void __launch_bounds__(256, 2)
sgemm_nn(const float* __restrict__ A, const float* __restrict__ Bm,
         const float* __restrict__ bias, const float* __restrict__ res,
         float* __restrict__ C, int M, int N, int K, int do_gelu) {
    __shared__ float As[8][128];
    __shared__ float Bs[8][128];
    const int tid  = threadIdx.x;
    const int row0 = blockIdx.y * 128, col0 = blockIdx.x * 128;
    const int ar = tid >> 1,  ac = (tid & 1) << 2;
    const int br = tid >> 5,  bc = (tid & 31) << 2;
    const int ty = tid >> 4,  tx = tid & 15;

    float acc[8][8];
#pragma unroll
    for (int i = 0; i < 8; i++)
#pragma unroll
        for (int j = 0; j < 8; j++) acc[i][j] = 0.0f;

    const float* Ap = A  + (size_t)(row0 + ar) * K + ac;
    const float* Bp = Bm + (size_t)br * N + col0 + bc;

    for (int k0 = 0; k0 < K; k0 += 8) {
        const float4 a4 = *(const float4*)Ap;  Ap += 8;
        const float4 b4 = *(const float4*)(Bp + (size_t)k0 * N);
        As[ac + 0][ar] = a4.x; As[ac + 1][ar] = a4.y;
        As[ac + 2][ar] = a4.z; As[ac + 3][ar] = a4.w;
        *(float4*)&Bs[br][bc] = b4;
        __syncthreads();
#pragma unroll
        for (int kk = 0; kk < 8; kk++) {
            float a[8], b[8];
            *(float4*)(a)     = *(const float4*)&As[kk][ty * 8];
            *(float4*)(a + 4) = *(const float4*)&As[kk][ty * 8 + 4];
            *(float4*)(b)     = *(const float4*)&Bs[kk][tx * 8];
            *(float4*)(b + 4) = *(const float4*)&Bs[kk][tx * 8 + 4];
#pragma unroll
            for (int i = 0; i < 8; i++)
#pragma unroll
                for (int j = 0; j < 8; j++)
                    acc[i][j] = fmaf(a[i], b[j], acc[i][j]);
        }
        __syncthreads();
    }

#pragma unroll
    for (int i = 0; i < 8; i++) {
        const int r = row0 + ty * 8 + i;
#pragma unroll
        for (int j = 0; j < 8; j += 4) {
            const int c = col0 + tx * 8 + j;
            float4 v;
            v.x = acc[i][j]; v.y = acc[i][j+1]; v.z = acc[i][j+2]; v.w = acc[i][j+3];
            if (bias) {
                const float4 bb = *(const float4*)(bias + c);
                v.x += bb.x; v.y += bb.y; v.z += bb.z; v.w += bb.w;
            }
            if (do_gelu) {
                v.x = 0.5f * v.x * (1.0f + erff(v.x * 0.7071067811865475f));
                v.y = 0.5f * v.y * (1.0f + erff(v.y * 0.7071067811865475f));
                v.z = 0.5f * v.z * (1.0f + erff(v.z * 0.7071067811865475f));
                v.w = 0.5f * v.w * (1.0f + erff(v.w * 0.7071067811865475f));
            }
            if (res) {
                const float4 rr = *(const float4*)(res + (size_t)r * N + c);
                v.x += rr.x; v.y += rr.y; v.z += rr.z; v.w += rr.w;
            }
            *(float4*)(C + (size_t)r * N + c) = v;
        }
    }
}

// ---------------------------------------------------------------------------
// Batched attention scores (NT): Sc[bh,i,j] = SCALE * sum_d Q[b,i,h,d]*K[b,j,h,d]
// 128x128 tile over (i,j), K-dim = HD = 64. Causal blocks fully above the
// diagonal band are skipped (their scores are never read by softmax).
// grid: (S/128, T/128, BH)
// ---------------------------------------------------------------------------
__global__ void __launch_bounds__(256, 2)
attn_scores(const float* __restrict__ Q, const float* __restrict__ Kt,
            float* __restrict__ Sc, int Tq, int Tk, int causal) {
    const int bh = blockIdx.z;
    const int b = bh >> 4, h = bh & 15;
    const int i0 = blockIdx.y * 128, j0 = blockIdx.x * 128;
    if (causal && j0 > i0 + 127) return;

    __shared__ float Qs[8][128];
    __shared__ float Ks[8][128];
    const int tid = threadIdx.x;
    const int ar = tid >> 1, ac = (tid & 1) << 2;
    const int ty = tid >> 4, tx = tid & 15;

    float acc[8][8];
#pragma unroll
    for (int i = 0; i < 8; i++)
#pragma unroll
        for (int j = 0; j < 8; j++) acc[i][j] = 0.0f;

    const float* Qp = Q  + (size_t)(b * Tq + i0 + ar) * cfg::E + h * cfg::HD + ac;
    const float* Kp = Kt + (size_t)(b * Tk + j0 + ar) * cfg::E + h * cfg::HD + ac;

    for (int k0 = 0; k0 < cfg::HD; k0 += 8) {
        const float4 a4 = *(const float4*)Qp;  Qp += 8;
        const float4 b4 = *(const float4*)Kp;  Kp += 8;
        Qs[ac + 0][ar] = a4.x; Qs[ac + 1][ar] = a4.y;
        Qs[ac + 2][ar] = a4.z; Qs[ac + 3][ar] = a4.w;
        Ks[ac + 0][ar] = b4.x; Ks[ac + 1][ar] = b4.y;
        Ks[ac + 2][ar] = b4.z; Ks[ac + 3][ar] = b4.w;
        __syncthreads();
#pragma unroll
        for (int kk = 0; kk < 8; kk++) {
            float a[8], b[8];
            *(float4*)(a)     = *(const float4*)&Qs[kk][ty * 8];
            *(float4*)(a + 4) = *(const float4*)&Qs[kk][ty * 8 + 4];
            *(float4*)(b)     = *(const float4*)&Ks[kk][tx * 8];
            *(float4*)(b + 4) = *(const float4*)&Ks[kk][tx * 8 + 4];
#pragma unroll
            for (int i = 0; i < 8; i++)
#pragma unroll
                for (int j = 0; j < 8; j++)
                    acc[i][j] = fmaf(a[i], b[j], acc[i][j]);
        }
        __syncthreads();
    }

    float* out = Sc + (size_t)bh * Tq * (size_t)Tk;
#pragma unroll
    for (int i = 0; i < 8; i++) {
        const int r = i0 + ty * 8 + i;
#pragma unroll
        for (int j = 0; j < 8; j += 4) {
            const int c = j0 + tx * 8 + j;
            float4 v;
            v.x = acc[i][j]     * cfg::SCALE;
            v.y = acc[i][j + 1] * cfg::SCALE;
            v.z = acc[i][j + 2] * cfg::SCALE;
            v.w = acc[i][j + 3] * cfg::SCALE;
            *(float4*)(out + (size_t)r * Tk + c) = v;
        }
    }
}

// ---------------------------------------------------------------------------
// Row softmax with causal mask. One block (256 threads) per row.
// Masked tail is written as 0 so attn_av can read it blindly.
// ---------------------------------------------------------------------------
__global__ void softmax_rows(float* __restrict__ P, int Tq, int Tk, int causal) {
    __shared__ float red[256];
    const size_t r = blockIdx.x;
    const int i = (int)(r % (unsigned)Tq);
    float* row = P + r * (size_t)Tk;
    const int len = causal ? (i + 1) : Tk;
    const int tid = threadIdx.x;

    float m = -3.4e38f;
    for (int j = tid; j < len; j += 256) m = fmaxf(m, row[j]);
    red[tid] = m; __syncthreads();
    for (int off = 128; off; off >>= 1) {
        if (tid < off) red[tid] = fmaxf(red[tid], red[tid + off]);
        __syncthreads();
    }
    m = red[0]; __syncthreads();

    float s = 0.0f;
    for (int j = tid; j < len; j += 256) {
        const float e = __expf(row[j] - m);
        row[j] = e;
        s += e;
    }
    red[tid] = s; __syncthreads();
    for (int off = 128; off; off >>= 1) {
        if (tid < off) red[tid] += red[tid + off];
        __syncthreads();
    }
    const float inv = 1.0f / red[0];

    for (int j = tid; j < len; j += 256) row[j] *= inv;
    for (int j = len + tid; j < Tk; j += 256) row[j] = 0.0f;
}

// ---------------------------------------------------------------------------
// Batched P@V: O[b,i,h,d] = sum_j P[bh,i,j] * V[b,j,h,d]
// 128(i) x 64(d) tile, BK=8 over j. Causal caps the j loop at i0+128
// (entries j>i within that range are exact zeros from softmax).
// grid: (T/128, BH)
// ---------------------------------------------------------------------------
__global__ void __launch_bounds__(256, 2)
attn_av(const float* __restrict__ P, const float* __restrict__ V,
        float* __restrict__ O, int Tq, int Tk, int causal) {
    const int bh = blockIdx.y;
    const int b = bh >> 4, h = bh & 15;
    const int i0 = blockIdx.x * 128;

    const float* Pb = P + (size_t)bh * Tq * (size_t)Tk;
    const float* Vb = V + (size_t)b * Tk * cfg::E + h * cfg::HD;
    float*       Ob = O + (size_t)b * Tq * cfg::E + h * cfg::HD;

    __shared__ float Ps[8][128];
    __shared__ float Vs[8][64];
    const int tid = threadIdx.x;
    const int ar = tid >> 1, ac = (tid & 1) << 2;
    const int ty = tid >> 4, tx = tid & 15;

    float acc[8][4];
#pragma unroll
    for (int i = 0; i < 8; i++)
#pragma unroll
        for (int j = 0; j < 4; j++) acc[i][j] = 0.0f;

    const int kmax = causal ? min(Tk, i0 + 128) : Tk;
    for (int k0 = 0; k0 < kmax; k0 += 8) {
        const float4 p4 = *(const float4*)(Pb + (size_t)(i0 + ar) * Tk + k0 + ac);
        Ps[ac + 0][ar] = p4.x; Ps[ac + 1][ar] = p4.y;
        Ps[ac + 2][ar] = p4.z; Ps[ac + 3][ar] = p4.w;
        if (tid < 128) {
            const int vr = tid >> 4, vc = (tid & 15) << 2;
            *(float4*)&Vs[vr][vc] =
                *(const float4*)(Vb + (size_t)(k0 + vr) * cfg::E + vc);
        }
        __syncthreads();
#pragma unroll
        for (int kk = 0; kk < 8; kk++) {
            float a[8], bv[4];
            *(float4*)(a)     = *(const float4*)&Ps[kk][ty * 8];
            *(float4*)(a + 4) = *(const float4*)&Ps[kk][ty * 8 + 4];
            *(float4*)(bv)    = *(const float4*)&Vs[kk][tx * 4];
#pragma unroll
            for (int i = 0; i < 8; i++)
#pragma unroll
                for (int j = 0; j < 4; j++)
                    acc[i][j] = fmaf(a[i], bv[j], acc[i][j]);
        }
        __syncthreads();
    }

#pragma unroll
    for (int i = 0; i < 8; i++) {
        const int r = i0 + ty * 8 + i;
        float4 v;
        v.x = acc[i][0]; v.y = acc[i][1]; v.z = acc[i][2]; v.w = acc[i][3];
        *(float4*)(Ob + (size_t)r * cfg::E + tx * 4) = v;
    }
}

// ---------------------------------------------------------------------------
// Launch sequence
// ---------------------------------------------------------------------------
extern "C" void kernel_launch(void* const* d_in, const int* in_sizes, int n_in,
                              void* d_out, int out_size) {
    using namespace cfg;
    const float* x        = (const float*)d_in[0];
    const float* context  = (const float*)d_in[1];
    const float* ln1_g    = (const float*)d_in[2];
    const float* ln1_b    = (const float*)d_in[3];
    const float* ln2_g    = (const float*)d_in[4];
    const float* ln2_b    = (const float*)d_in[5];
    const float* ln3_g    = (const float*)d_in[6];
    const float* ln3_b    = (const float*)d_in[7];
    const float* Wq_s     = (const float*)d_in[8];
    const float* Wk_s     = (const float*)d_in[9];
    const float* Wv_s     = (const float*)d_in[10];
    const float* proj_s_w = (const float*)d_in[11];
    const float* proj_s_b = (const float*)d_in[12];
    const float* Wq_c     = (const float*)d_in[13];
    const float* Wk_c     = (const float*)d_in[14];
    const float* Wv_c     = (const float*)d_in[15];
    const float* proj_c_w = (const float*)d_in[16];
    const float* proj_c_b = (const float*)d_in[17];
    const float* w1       = (const float*)d_in[18];
    const float* b1       = (const float*)d_in[19];
    const float* w2       = (const float*)d_in[20];
    const float* b2       = (const float*)d_in[21];
    float* out = (float*)d_out;

    float *ph, *pq, *pk, *pv, *pa, *px1, *px2, *pffn, *psc;
    cudaGetSymbolAddress((void**)&ph,   g_h);
    cudaGetSymbolAddress((void**)&pq,   g_q);
    cudaGetSymbolAddress((void**)&pk,   g_k);
    cudaGetSymbolAddress((void**)&pv,   g_v);
    cudaGetSymbolAddress((void**)&pa,   g_a);
    cudaGetSymbolAddress((void**)&px1,  g_x1);
    cudaGetSymbolAddress((void**)&px2,  g_x2);
    cudaGetSymbolAddress((void**)&pffn, g_ffn);
    cudaGetSymbolAddress((void**)&psc,  g_sc);

    const int M = B * T;                       // 4096 rows for x-side
    const dim3 gE  (E / 128,     M / 128);     // (8, 32)
    const dim3 g4E (4 * E / 128, M / 128);     // (32, 32)
    const dim3 gsc (S / 128, T / 128, BH);     // (16, 16, 32)
    const dim3 gav (T / 128, BH);              // (16, 32)

    // ---- self attention (causal) ----
    ln_kernel<<<M, 256>>>(x, ln1_g, ln1_b, ph);
    sgemm_nn<<<gE, 256>>>(ph, Wq_s, nullptr, nullptr, pq, M, E, E, 0);
    sgemm_nn<<<gE, 256>>>(ph, Wk_s, nullptr, nullptr, pk, M, E, E, 0);
    sgemm_nn<<<gE, 256>>>(ph, Wv_s, nullptr, nullptr, pv, M, E, E, 0);
    attn_scores<<<gsc, 256>>>(pq, pk, psc, T, S, 1);
    softmax_rows<<<BH * T, 256>>>(psc, T, S, 1);
    attn_av<<<gav, 256>>>(psc, pv, pa, T, S, 1);
    sgemm_nn<<<gE, 256>>>(pa, proj_s_w, proj_s_b, x, px1, M, E, E, 0);

    // ---- cross attention (context not normalized) ----
    ln_kernel<<<M, 256>>>(px1, ln2_g, ln2_b, ph);
    sgemm_nn<<<gE, 256>>>(ph,      Wq_c, nullptr, nullptr, pq, M,     E, E, 0);
    sgemm_nn<<<gE, 256>>>(context, Wk_c, nullptr, nullptr, pk, B * S, E, E, 0);
    sgemm_nn<<<gE, 256>>>(context, Wv_c, nullptr, nullptr, pv, B * S, E, E, 0);
    attn_scores<<<gsc, 256>>>(pq, pk, psc, T, S, 0);
    softmax_rows<<<BH * T, 256>>>(psc, T, S, 0);
    attn_av<<<gav, 256>>>(psc, pv, pa, T, S, 0);
    sgemm_nn<<<gE, 256>>>(pa, proj_c_w, proj_c_b, px1, px2, M, E, E, 0);

    // ---- FFN (exact GELU) ----
    ln_kernel<<<M, 256>>>(px2, ln3_g, ln3_b, ph);
    sgemm_nn<<<g4E, 256>>>(ph, w1, b1, nullptr, pffn, M, 4 * E, E, 1);
    sgemm_nn<<<gE, 256>>>(pffn, w2, b2, px2, out, M, E, 4 * E, 0);
}

// round 3
// speedup vs baseline: 1.7162x; 1.7162x over previous
#include <cuda_runtime.h>
#include <cuda_bf16.h>
#include <math.h>
#include <stdint.h>

// ---------------------------------------------------------------------------
// DecoderLayerWithContext — Round 3
// Tensor cores via arch-portable mma.sync (HMMA) — tcgen05 rejected because
// the harness compiles at virtual arch compute_100 (no 'a').
// bf16x3 split (hi/lo) for fp32-grade precision. cp.async double buffering.
// Dense GEMMs + QK^T scores on HMMA; softmax/AV still fp32 SIMT.
// ---------------------------------------------------------------------------

namespace cfg {
constexpr int E  = 1024;
constexpr int NH = 16;
constexpr int HD = 64;
constexpr int B  = 2;
constexpr int T  = 2048;
constexpr int S  = 2048;
constexpr int BH = B * NH;
constexpr float SCALE = 0.03125f;  // 1/sqrt(1024)
}

// -------------------------- device scratch ---------------------------------
__device__ float g_v  [cfg::B * cfg::S * cfg::E];
__device__ float g_x1 [cfg::B * cfg::T * cfg::E];
__device__ float g_x2 [cfg::B * cfg::T * cfg::E];
__device__ float g_sc [(size_t)cfg::BH * cfg::T * cfg::S];
// bf16 split operands
__device__ uint16_t g_ahi[(size_t)16 * 1024 * 1024];  // act [0,4M), ctx [8M,12M)
__device__ uint16_t g_alo[(size_t)16 * 1024 * 1024];
__device__ uint16_t g_bhi[(size_t)4 * 1024 * 1024];
__device__ uint16_t g_blo[(size_t)4 * 1024 * 1024];
__device__ uint16_t g_qhi[(size_t)4 * 1024 * 1024];
__device__ uint16_t g_qlo[(size_t)4 * 1024 * 1024];
__device__ uint16_t g_khi[(size_t)4 * 1024 * 1024];
__device__ uint16_t g_klo[(size_t)4 * 1024 * 1024];
__device__ uint16_t g_fhi[(size_t)16 * 1024 * 1024];
__device__ uint16_t g_flo[(size_t)16 * 1024 * 1024];

// -------------------------- asm helpers ------------------------------------
__device__ __forceinline__ uint32_t smem_u32(const void* p) {
    uint32_t a;
    asm("{ .reg .u64 t; cvta.to.shared.u64 t, %1; cvt.u32.u64 %0, t; }" : "=r"(a) : "l"(p));
    return a;
}
#define CP16(s, g) \
    asm volatile("cp.async.cg.shared.global [%0], [%1], 16;" :: "r"(s), "l"(g))
#define CP_COMMIT()  asm volatile("cp.async.commit_group;" ::: "memory")
#define CP_WAIT0()   asm volatile("cp.async.wait_group 0;" ::: "memory")
#define CP_WAIT1()   asm volatile("cp.async.wait_group 1;" ::: "memory")

#define LDSM4(r, addr)                                                        \
    asm volatile("ldmatrix.sync.aligned.m8n8.x4.shared.b16 {%0,%1,%2,%3}, [%4];" \
        : "=r"((r)[0]), "=r"((r)[1]), "=r"((r)[2]), "=r"((r)[3]) : "r"(addr))

#define MMA16816(d, a, b0, b1)                                                \
    asm volatile("mma.sync.aligned.m16n8k16.row.col.f32.bf16.bf16.f32 "       \
        "{%0,%1,%2,%3},{%4,%5,%6,%7},{%8,%9},{%0,%1,%2,%3};"                  \
        : "+f"((d)[0]), "+f"((d)[1]), "+f"((d)[2]), "+f"((d)[3])              \
        : "r"((a)[0]), "r"((a)[1]), "r"((a)[2]), "r"((a)[3]), "r"(b0), "r"(b1))

__device__ __forceinline__ void bsplit(float x, unsigned short& h, unsigned short& l) {
    __nv_bfloat16 hb = __float2bfloat16(x);
    __nv_bfloat16 lb = __float2bfloat16(x - __bfloat162float(hb));
    h = *reinterpret_cast<unsigned short*>(&hb);
    l = *reinterpret_cast<unsigned short*>(&lb);
}
__device__ __forceinline__ float gelu_f(float x) {
    return 0.5f * x * (1.0f + erff(x * 0.7071067811865475f));
}

// SMEM stage layout: Ah | Al | Bh | Bl, each 128 rows x 128 bytes (16 KB)
constexpr int OFF_AH = 0;
constexpr int OFF_AL = 16384;
constexpr int OFF_BH = 32768;
constexpr int OFF_BL = 49152;
constexpr int STAGE_BYTES = 65536;

// ---------------------------------------------------------------------------
// HMMA GEMM: C[M,N](+epi) = A[M,K] * B[N,K]^T with bf16x3 split operands.
// Tile 128x128, K chunks of 64, 8 warps (2x4) of 64x32, double-buffered.
// grid (N/128, M/128), block 256.
// ---------------------------------------------------------------------------
__global__ void __launch_bounds__(256, 1)
tc_gemm(const uint16_t* __restrict__ Ahi, const uint16_t* __restrict__ Alo,
        const uint16_t* __restrict__ Bhi, const uint16_t* __restrict__ Blo,
        const float* __restrict__ bias, const float* __restrict__ res,
        float* __restrict__ C, uint16_t* __restrict__ Chi, uint16_t* __restrict__ Clo,
        int N, int K, int do_gelu) {
    extern __shared__ uint8_t dsm[];
    uint8_t* tiles = (uint8_t*)(((uintptr_t)dsm + 1023) & ~(uintptr_t)1023);
    const uint32_t tb = smem_u32(tiles);

    const int tid  = threadIdx.x;
    const int lane = tid & 31;
    const int wid  = tid >> 5;
    const int wr   = wid >> 2;   // 0..1
    const int wc   = wid & 3;    // 0..3
    const int row0 = blockIdx.y * 128;
    const int col0 = blockIdx.x * 128;

    // ---- load geometry (SW128 swizzle) ----
    const int lrow = tid >> 1, lhalf = tid & 1;
    uint32_t so[4];
#pragma unroll
    for (int i = 0; i < 4; i++) {
        uint32_t o = (uint32_t)lrow * 128 + (uint32_t)lhalf * 64 + i * 16;
        so[i] = o ^ ((o >> 3) & 0x70);
    }
    const size_t a_base = (size_t)(row0 + lrow) * K + lhalf * 32;
    const size_t b_base = (size_t)(col0 + lrow) * K + lhalf * 32;

    // ---- fragment address geometry ----
    const int ka = (lane >> 4) * 16;          // A col-byte sub-offset
    const int kb = ((lane >> 3) & 1) * 16;    // B col-byte sub-offset
    uint32_t aoff[4], xA[4];
#pragma unroll
    for (int mt = 0; mt < 4; mt++) {
        int r = wr * 64 + mt * 16 + (lane & 15);
        aoff[mt] = (uint32_t)r * 128;
        xA[mt] = (uint32_t)(r & 7) * 16;
    }
    uint32_t boff[2], xB[2];
#pragma unroll
    for (int p = 0; p < 2; p++) {
        int r = wc * 32 + p * 16 + ((lane >> 4) & 1) * 8 + (lane & 7);
        boff[p] = (uint32_t)r * 128;
        xB[p] = (uint32_t)(r & 7) * 16;
    }

    float acc[4][4][4];
#pragma unroll
    for (int mt = 0; mt < 4; mt++)
#pragma unroll
        for (int nt = 0; nt < 4; nt++)
#pragma unroll
            for (int e = 0; e < 4; e++) acc[mt][nt][e] = 0.0f;

    const int NC = K >> 6;

    // prologue: stage 0
    {
        const uint32_t st = tb;
#pragma unroll
        for (int i = 0; i < 4; i++) {
            CP16(st + OFF_AH + so[i], Ahi + a_base + i * 8);
            CP16(st + OFF_AL + so[i], Alo + a_base + i * 8);
            CP16(st + OFF_BH + so[i], Bhi + b_base + i * 8);
            CP16(st + OFF_BL + so[i], Blo + b_base + i * 8);
        }
        CP_COMMIT();
    }

    for (int c = 0; c < NC; c++) {
        if (c + 1 < NC) {
            const uint32_t st = tb + ((c + 1) & 1) * STAGE_BYTES;
            const int kc = (c + 1) << 6;
#pragma unroll
            for (int i = 0; i < 4; i++) {
                CP16(st + OFF_AH + so[i], Ahi + a_base + kc + i * 8);
                CP16(st + OFF_AL + so[i], Alo + a_base + kc + i * 8);
                CP16(st + OFF_BH + so[i], Bhi + b_base + kc + i * 8);
                CP16(st + OFF_BL + so[i], Blo + b_base + kc + i * 8);
            }
            CP_COMMIT();
            CP_WAIT1();
        } else {
            CP_WAIT0();
        }
        __syncthreads();

        const uint32_t sb = tb + (c & 1) * STAGE_BYTES;
#pragma unroll
        for (int ks = 0; ks < 4; ks++) {
            uint32_t ah[4][4], al[4][4], bh[2][4], bl[2][4];
            const uint32_t cba = (uint32_t)(ks * 32 + ka);
#pragma unroll
            for (int mt = 0; mt < 4; mt++) {
                const uint32_t off = aoff[mt] + (cba ^ xA[mt]);
                LDSM4(ah[mt], sb + OFF_AH + off);
                LDSM4(al[mt], sb + OFF_AL + off);
            }
            const uint32_t cbb = (uint32_t)(ks * 32 + kb);
#pragma unroll
            for (int p = 0; p < 2; p++) {
                const uint32_t off = boff[p] + (cbb ^ xB[p]);
                LDSM4(bh[p], sb + OFF_BH + off);
                LDSM4(bl[p], sb + OFF_BL + off);
            }
#pragma unroll
            for (int mt = 0; mt < 4; mt++)
#pragma unroll
                for (int nt = 0; nt < 4; nt++) {
                    const int p = nt >> 1, q = (nt & 1) * 2;
                    MMA16816(acc[mt][nt], ah[mt], bh[p][q], bh[p][q + 1]);
                    MMA16816(acc[mt][nt], ah[mt], bl[p][q], bl[p][q + 1]);
                    MMA16816(acc[mt][nt], al[mt], bh[p][q], bh[p][q + 1]);
                }
        }
        __syncthreads();
    }

    // ---- epilogue ----
    const int mrow = lane >> 2;
    const int ncol = (lane & 3) * 2;
#pragma unroll
    for (int mt = 0; mt < 4; mt++) {
#pragma unroll
        for (int half = 0; half < 2; half++) {
            const int r = row0 + wr * 64 + mt * 16 + mrow + half * 8;
#pragma unroll
            for (int nt = 0; nt < 4; nt++) {
                float v0 = acc[mt][nt][half * 2 + 0];
                float v1 = acc[mt][nt][half * 2 + 1];
                const int cc = col0 + wc * 32 + nt * 8 + ncol;
                if (bias) { v0 += bias[cc]; v1 += bias[cc + 1]; }
                if (do_gelu) { v0 = gelu_f(v0); v1 = gelu_f(v1); }
                if (res) {
                    v0 += res[(size_t)r * N + cc];
                    v1 += res[(size_t)r * N + cc + 1];
                }
                if (C) *(float2*)(C + (size_t)r * N + cc) = make_float2(v0, v1);
                if (Chi) {
                    unsigned short h0, l0, h1, l1;
                    bsplit(v0, h0, l0);
                    bsplit(v1, h1, l1);
                    *(uint32_t*)(Chi + (size_t)r * N + cc) = (uint32_t)h0 | ((uint32_t)h1 << 16);
                    *(uint32_t*)(Clo + (size_t)r * N + cc) = (uint32_t)l0 | ((uint32_t)l1 << 16);
                }
            }
        }
    }
}

// ---------------------------------------------------------------------------
// HMMA batched scores: Sc[bh,i,j] = SCALE * sum_d Q[b,i,h,d]*K[b,j,h,d]
// Single 64-deep K chunk. grid (Tk/128, Tq/128, BH), block 256.
// ---------------------------------------------------------------------------
__global__ void __launch_bounds__(256, 1)
attn_scores_mma(const uint16_t* __restrict__ Qhi, const uint16_t* __restrict__ Qlo,
                const uint16_t* __restrict__ Khi, const uint16_t* __restrict__ Klo,
                float* __restrict__ Sc, int Tq, int Tk, int causal) {
    const int bh = blockIdx.z;
    const int b = bh >> 4, h = bh & 15;
    const int i0 = blockIdx.y * 128, j0 = blockIdx.x * 128;
    if (causal && j0 > i0 + 127) return;

    extern __shared__ uint8_t dsm[];
    uint8_t* tiles = (uint8_t*)(((uintptr_t)dsm + 1023) & ~(uintptr_t)1023);
    const uint32_t tb = smem_u32(tiles);

    const int tid  = threadIdx.x;
    const int lane = tid & 31;
    const int wid  = tid >> 5;
    const int wr   = wid >> 2;
    const int wc   = wid & 3;

    const int lrow = tid >> 1, lhalf = tid & 1;
    uint32_t so[4];
#pragma unroll
    for (int i = 0; i < 4; i++) {
        uint32_t o = (uint32_t)lrow * 128 + (uint32_t)lhalf * 64 + i * 16;
        so[i] = o ^ ((o >> 3) & 0x70);
    }
    const size_t qoff = (size_t)(b * Tq + i0 + lrow) * cfg::E + h * cfg::HD + lhalf * 32;
    const size_t koff = (size_t)(b * Tk + j0 + lrow) * cfg::E + h * cfg::HD + lhalf * 32;
#pragma unroll
    for (int i = 0; i < 4; i++) {
        CP16(tb + OFF_AH + so[i], Qhi + qoff + i * 8);
        CP16(tb + OFF_AL + so[i], Qlo + qoff + i * 8);
        CP16(tb + OFF_BH + so[i], Khi + koff + i * 8);
        CP16(tb + OFF_BL + so[i], Klo + koff + i * 8);
    }
    CP_COMMIT();

    const int ka = (lane >> 4) * 16;
    const int kb = ((lane >> 3) & 1) * 16;
    uint32_t aoff[4], xA[4];
#pragma unroll
    for (int mt = 0; mt < 4; mt++) {
        int r = wr * 64 + mt * 16 + (lane & 15);
        aoff[mt] = (uint32_t)r * 128;
        xA[mt] = (uint32_t)(r & 7) * 16;
    }
    uint32_t boff[2], xB[2];
#pragma unroll
    for (int p = 0; p < 2; p++) {
        int r = wc * 32 + p * 16 + ((lane >> 4) & 1) * 8 + (lane & 7);
        boff[p] = (uint32_t)r * 128;
        xB[p] = (uint32_t)(r & 7) * 16;
    }

    float acc[4][4][4];
#pragma unroll
    for (int mt = 0; mt < 4; mt++)
#pragma unroll
        for (int nt = 0; nt < 4; nt++)
#pragma unroll
            for (int e = 0; e < 4; e++) acc[mt][nt][e] = 0.0f;

    CP_WAIT0();
    __syncthreads();

#pragma unroll
    for (int ks = 0; ks < 4; ks++) {
        uint32_t ah[4][4], al[4][4], bh[2][4], bl[2][4];
        const uint32_t cba = (uint32_t)(ks * 32 + ka);
#pragma unroll
        for (int mt = 0; mt < 4; mt++) {
            const uint32_t off = aoff[mt] + (cba ^ xA[mt]);
            LDSM4(ah[mt], tb + OFF_AH + off);
            LDSM4(al[mt], tb + OFF_AL + off);
        }
        const uint32_t cbb = (uint32_t)(ks * 32 + kb);
#pragma unroll
        for (int p = 0; p < 2; p++) {
            const uint32_t off = boff[p] + (cbb ^ xB[p]);
            LDSM4(bh[p], tb + OFF_BH + off);
            LDSM4(bl[p], tb + OFF_BL + off);
        }
#pragma unroll
        for (int mt = 0; mt < 4; mt++)
#pragma unroll
            for (int nt = 0; nt < 4; nt++) {
                const int p = nt >> 1, q = (nt & 1) * 2;
                MMA16816(acc[mt][nt], ah[mt], bh[p][q], bh[p][q + 1]);
                MMA16816(acc[mt][nt], ah[mt], bl[p][q], bl[p][q + 1]);
                MMA16816(acc[mt][nt], al[mt], bh[p][q], bh[p][q + 1]);
            }
    }

    float* out = Sc + (size_t)bh * Tq * (size_t)Tk;
    const int mrow = lane >> 2;
    const int ncol = (lane & 3) * 2;
#pragma unroll
    for (int mt = 0; mt < 4; mt++)
#pragma unroll
        for (int half = 0; half < 2; half++) {
            const int r = i0 + wr * 64 + mt * 16 + mrow + half * 8;
#pragma unroll
            for (int nt = 0; nt < 4; nt++) {
                const int cc = j0 + wc * 32 + nt * 8 + ncol;
                float2 v;
                v.x = acc[mt][nt][half * 2 + 0] * cfg::SCALE;
                v.y = acc[mt][nt][half * 2 + 1] * cfg::SCALE;
                *(float2*)(out + (size_t)r * Tk + cc) = v;
            }
        }
}

// ---------------------------------------------------------------------------
// LayerNorm emitting bf16 hi/lo split directly
// ---------------------------------------------------------------------------
__global__ void ln_split(const float* __restrict__ X, const float* __restrict__ gam,
                         const float* __restrict__ bet, uint16_t* __restrict__ Hi,
                         uint16_t* __restrict__ Lo) {
    __shared__ float red[256];
    const int row = blockIdx.x;
    const int tid = threadIdx.x;
    const float4 v = ((const float4*)(X + (size_t)row * cfg::E))[tid];

    float s = v.x + v.y + v.z + v.w;
    red[tid] = s; __syncthreads();
    for (int off = 128; off; off >>= 1) {
        if (tid < off) red[tid] += red[tid + off];
        __syncthreads();
    }
    const float mu = red[0] * (1.0f / cfg::E);
    __syncthreads();

    const float dx = v.x - mu, dy = v.y - mu, dz = v.z - mu, dw = v.w - mu;
    red[tid] = dx*dx + dy*dy + dz*dz + dw*dw; __syncthreads();
    for (int off = 128; off; off >>= 1) {
        if (tid < off) red[tid] += red[tid + off];
        __syncthreads();
    }
    const float var = red[0] * (1.0f / cfg::E);
    const float r = rsqrtf(var + 1e-5f);

    const float4 g4 = ((const float4*)gam)[tid];
    const float4 b4 = ((const float4*)bet)[tid];
    float o[4];
    o[0] = dx * r * g4.x + b4.x;
    o[1] = dy * r * g4.y + b4.y;
    o[2] = dz * r * g4.z + b4.z;
    o[3] = dw * r * g4.w + b4.w;
    ushort4 ho, lo;
    unsigned short hs[4], ls[4];
#pragma unroll
    for (int c = 0; c < 4; c++) bsplit(o[c], hs[c], ls[c]);
    ho.x = hs[0]; ho.y = hs[1]; ho.z = hs[2]; ho.w = hs[3];
    lo.x = ls[0]; lo.y = ls[1]; lo.z = ls[2]; lo.w = ls[3];
    ((ushort4*)(Hi + (size_t)row * cfg::E))[tid] = ho;
    ((ushort4*)(Lo + (size_t)row * cfg::E))[tid] = lo;
}

// ---------------------------------------------------------------------------
// fp32 -> bf16 hi/lo split (for context input)
// ---------------------------------------------------------------------------
__global__ void split_f32(const float* __restrict__ X, uint16_t* __restrict__ Hi,
                          uint16_t* __restrict__ Lo, int n4) {
    const int i = blockIdx.x * 256 + threadIdx.x;
    if (i >= n4) return;
    const float4 v = ((const float4*)X)[i];
    float xs[4] = {v.x, v.y, v.z, v.w};
    unsigned short hs[4], ls[4];
#pragma unroll
    for (int c = 0; c < 4; c++) bsplit(xs[c], hs[c], ls[c]);
    ushort4 ho, lo;
    ho.x = hs[0]; ho.y = hs[1]; ho.z = hs[2]; ho.w = hs[3];
    lo.x = ls[0]; lo.y = ls[1]; lo.z = ls[2]; lo.w = ls[3];
    ((ushort4*)Hi)[i] = ho;
    ((ushort4*)Lo)[i] = lo;
}

// ---------------------------------------------------------------------------
// W[K,N] fp32 -> [N,K] bf16 hi/lo (transpose + split)
// grid (N/32, K/32), block (32, 8)
// ---------------------------------------------------------------------------
__global__ void transpose_split(const float* __restrict__ W, uint16_t* __restrict__ Hi,
                                uint16_t* __restrict__ Lo, int Kd, int Nd) {
    __shared__ float tile[32][33];
    const int n0 = blockIdx.x * 32, k0 = blockIdx.y * 32;
    const int tx = threadIdx.x, ty = threadIdx.y;
    for (int r = ty; r < 32; r += 8)
        tile[r][tx] = W[(size_t)(k0 + r) * Nd + n0 + tx];
    __syncthreads();
    for (int r = ty; r < 32; r += 8) {
        const float x = tile[tx][r];
        unsigned short h, l;
        bsplit(x, h, l);
        const size_t o = (size_t)(n0 + r) * Kd + k0 + tx;
        Hi[o] = h;
        Lo[o] = l;
    }
}

// ---------------------------------------------------------------------------
// Row softmax, causal mask; zero-fill only to the 128-block boundary.
// ---------------------------------------------------------------------------
__global__ void softmax_rows(float* __restrict__ P, int Tq, int Tk, int causal) {
    __shared__ float red[256];
    const size_t r = blockIdx.x;
    const int i = (int)(r % (unsigned)Tq);
    float* row = P + r * (size_t)Tk;
    const int len = causal ? (i + 1) : Tk;
    const int zend = causal ? min(Tk, (i & ~127) + 128) : Tk;
    const int tid = threadIdx.x;

    float m = -3.4e38f;
    for (int j = tid; j < len; j += 256) m = fmaxf(m, row[j]);
    red[tid] = m; __syncthreads();
    for (int off = 128; off; off >>= 1) {
        if (tid < off) red[tid] = fmaxf(red[tid], red[tid + off]);
        __syncthreads();
    }
    m = red[0]; __syncthreads();

    float s = 0.0f;
    for (int j = tid; j < len; j += 256) {
        const float e = __expf(row[j] - m);
        row[j] = e;
        s += e;
    }
    red[tid] = s; __syncthreads();
    for (int off = 128; off; off >>= 1) {
        if (tid < off) red[tid] += red[tid + off];
        __syncthreads();
    }
    const float inv = 1.0f / red[0];

    for (int j = tid; j < len; j += 256) row[j] *= inv;
    for (int j = len + tid; j < zend; j += 256) row[j] = 0.0f;
}

// ---------------------------------------------------------------------------
// P@V (fp32), emits bf16 hi/lo split of output (feeds projection GEMM).
// ---------------------------------------------------------------------------
__global__ void __launch_bounds__(256, 2)
attn_av(const float* __restrict__ P, const float* __restrict__ V,
        uint16_t* __restrict__ Ohi, uint16_t* __restrict__ Olo,
        int Tq, int Tk, int causal) {
    const int bh = blockIdx.y;
    const int b = bh >> 4, h = bh & 15;
    const int i0 = blockIdx.x * 128;

    const float* Pb = P + (size_t)bh * Tq * (size_t)Tk;
    const float* Vb = V + (size_t)b * Tk * cfg::E + h * cfg::HD;

    __shared__ float Ps[8][128];
    __shared__ float Vs[8][64];
    const int tid = threadIdx.x;
    const int ar = tid >> 1, ac = (tid & 1) << 2;
    const int ty = tid >> 4, tx = tid & 15;

    float acc[8][4];
#pragma unroll
    for (int i = 0; i < 8; i++)
#pragma unroll
        for (int j = 0; j < 4; j++) acc[i][j] = 0.0f;

    const int kmax = causal ? min(Tk, i0 + 128) : Tk;
    for (int k0 = 0; k0 < kmax; k0 += 8) {
        const float4 p4 = *(const float4*)(Pb + (size_t)(i0 + ar) * Tk + k0 + ac);
        Ps[ac + 0][ar] = p4.x; Ps[ac + 1][ar] = p4.y;
        Ps[ac + 2][ar] = p4.z; Ps[ac + 3][ar] = p4.w;
        if (tid < 128) {
            const int vr = tid >> 4, vc = (tid & 15) << 2;
            *(float4*)&Vs[vr][vc] =
                *(const float4*)(Vb + (size_t)(k0 + vr) * cfg::E + vc);
        }
        __syncthreads();
#pragma unroll
        for (int kk = 0; kk < 8; kk++) {
            float a[8], bv[4];
            *(float4*)(a)     = *(const float4*)&Ps[kk][ty * 8];
            *(float4*)(a + 4) = *(const float4*)&Ps[kk][ty * 8 + 4];
            *(float4*)(bv)    = *(const float4*)&Vs[kk][tx * 4];
#pragma unroll
            for (int i = 0; i < 8; i++)
#pragma unroll
                for (int j = 0; j < 4; j++)
                    acc[i][j] = fmaf(a[i], bv[j], acc[i][j]);
        }
        __syncthreads();
    }

#pragma unroll
    for (int i = 0; i < 8; i++) {
        const int r = i0 + ty * 8 + i;
        unsigned short hs[4], ls[4];
#pragma unroll
        for (int j = 0; j < 4; j++) bsplit(acc[i][j], hs[j], ls[j]);
        ushort4 ho, lo;
        ho.x = hs[0]; ho.y = hs[1]; ho.z = hs[2]; ho.w = hs[3];
        lo.x = ls[0]; lo.y = ls[1]; lo.z = ls[2]; lo.w = ls[3];
        const size_t o = (size_t)b * Tq * cfg::E + (size_t)r * cfg::E + h * cfg::HD + tx * 4;
        *(ushort4*)(Ohi + o) = ho;
        *(ushort4*)(Olo + o) = lo;
    }
}

// ---------------------------------------------------------------------------
// Launch sequence
// ---------------------------------------------------------------------------
extern "C" void kernel_launch(void* const* d_in, const int* in_sizes, int n_in,
                              void* d_out, int out_size) {
    using namespace cfg;
    const float* x        = (const float*)d_in[0];
    const float* context  = (const float*)d_in[1];
    const float* ln1_g    = (const float*)d_in[2];
    const float* ln1_b    = (const float*)d_in[3];
    const float* ln2_g    = (const float*)d_in[4];
    const float* ln2_b    = (const float*)d_in[5];
    const float* ln3_g    = (const float*)d_in[6];
    const float* ln3_b    = (const float*)d_in[7];
    const float* Wq_s     = (const float*)d_in[8];
    const float* Wk_s     = (const float*)d_in[9];
    const float* Wv_s     = (const float*)d_in[10];
    const float* proj_s_w = (const float*)d_in[11];
    const float* proj_s_b = (const float*)d_in[12];
    const float* Wq_c     = (const float*)d_in[13];
    const float* Wk_c     = (const float*)d_in[14];
    const float* Wv_c     = (const float*)d_in[15];
    const float* proj_c_w = (const float*)d_in[16];
    const float* proj_c_b = (const float*)d_in[17];
    const float* w1       = (const float*)d_in[18];
    const float* b1       = (const float*)d_in[19];
    const float* w2       = (const float*)d_in[20];
    const float* b2       = (const float*)d_in[21];
    float* out = (float*)d_out;

    float *pv, *px1, *px2, *psc;
    uint16_t *ahi, *alo, *bhi, *blo, *qhi, *qlo, *khi, *klo, *fhi, *flo;
    cudaGetSymbolAddress((void**)&pv,  g_v);
    cudaGetSymbolAddress((void**)&px1, g_x1);
    cudaGetSymbolAddress((void**)&px2, g_x2);
    cudaGetSymbolAddress((void**)&psc, g_sc);
    cudaGetSymbolAddress((void**)&ahi, g_ahi);
    cudaGetSymbolAddress((void**)&alo, g_alo);
    cudaGetSymbolAddress((void**)&bhi, g_bhi);
    cudaGetSymbolAddress((void**)&blo, g_blo);
    cudaGetSymbolAddress((void**)&qhi, g_qhi);
    cudaGetSymbolAddress((void**)&qlo, g_qlo);
    cudaGetSymbolAddress((void**)&khi, g_khi);
    cudaGetSymbolAddress((void**)&klo, g_klo);
    cudaGetSymbolAddress((void**)&fhi, g_fhi);
    cudaGetSymbolAddress((void**)&flo, g_flo);
    uint16_t* chi = ahi + (size_t)8 * 1024 * 1024;  // context split region
    uint16_t* clo = alo + (size_t)8 * 1024 * 1024;

    const int GEMM_SMEM = 2 * STAGE_BYTES + 1024;
    const int SC_SMEM   = STAGE_BYTES + 1024;
    cudaFuncSetAttribute(tc_gemm, cudaFuncAttributeMaxDynamicSharedMemorySize, GEMM_SMEM);
    cudaFuncSetAttribute(attn_scores_mma, cudaFuncAttributeMaxDynamicSharedMemorySize, SC_SMEM);

    const int M = B * T;                        // 4096
    const dim3 gE  (E / 128,     M / 128);
    const dim3 g4E (4 * E / 128, M / 128);
    const dim3 gsc (S / 128, T / 128, BH);
    const dim3 gav (T / 128, BH);
    const int nME4 = (M * E) / 4;
    const dim3 gtEE (E / 32, E / 32);
    const dim3 gtE4 (4 * E / 32, E / 32);
    const dim3 gt4E (E / 32, 4 * E / 32);
    const dim3 tb(32, 8);

    // ---- self attention (causal) ----
    ln_split<<<M, 256>>>(x, ln1_g, ln1_b, ahi, alo);
    transpose_split<<<gtEE, tb>>>(Wq_s, bhi, blo, E, E);
    tc_gemm<<<gE, 256, GEMM_SMEM>>>(ahi, alo, bhi, blo, nullptr, nullptr,
                                    nullptr, qhi, qlo, E, E, 0);
    transpose_split<<<gtEE, tb>>>(Wk_s, bhi, blo, E, E);
    tc_gemm<<<gE, 256, GEMM_SMEM>>>(ahi, alo, bhi, blo, nullptr, nullptr,
                                    nullptr, khi, klo, E, E, 0);
    transpose_split<<<gtEE, tb>>>(Wv_s, bhi, blo, E, E);
    tc_gemm<<<gE, 256, GEMM_SMEM>>>(ahi, alo, bhi, blo, nullptr, nullptr,
                                    pv, nullptr, nullptr, E, E, 0);
    attn_scores_mma<<<gsc, 256, SC_SMEM>>>(qhi, qlo, khi, klo, psc, T, S, 1);
    softmax_rows<<<BH * T, 256>>>(psc, T, S, 1);
    attn_av<<<gav, 256>>>(psc, pv, ahi, alo, T, S, 1);
    transpose_split<<<gtEE, tb>>>(proj_s_w, bhi, blo, E, E);
    tc_gemm<<<gE, 256, GEMM_SMEM>>>(ahi, alo, bhi, blo, proj_s_b, x,
                                    px1, nullptr, nullptr, E, E, 0);

    // ---- cross attention (context NOT normalized) ----
    ln_split<<<M, 256>>>(px1, ln2_g, ln2_b, ahi, alo);
    transpose_split<<<gtEE, tb>>>(Wq_c, bhi, blo, E, E);
    tc_gemm<<<gE, 256, GEMM_SMEM>>>(ahi, alo, bhi, blo, nullptr, nullptr,
                                    nullptr, qhi, qlo, E, E, 0);
    split_f32<<<(nME4 + 255) / 256, 256>>>(context, chi, clo, nME4);
    transpose_split<<<gtEE, tb>>>(Wk_c, bhi, blo, E, E);
    tc_gemm<<<gE, 256, GEMM_SMEM>>>(chi, clo, bhi, blo, nullptr, nullptr,
                                    nullptr, khi, klo, E, E, 0);
    transpose_split<<<gtEE, tb>>>(Wv_c, bhi, blo, E, E);
    tc_gemm<<<gE, 256, GEMM_SMEM>>>(chi, clo, bhi, blo, nullptr, nullptr,
                                    pv, nullptr, nullptr, E, E, 0);
    attn_scores_mma<<<gsc, 256, SC_SMEM>>>(qhi, qlo, khi, klo, psc, T, S, 0);
    softmax_rows<<<BH * T, 256>>>(psc, T, S, 0);
    attn_av<<<gav, 256>>>(psc, pv, ahi, alo, T, S, 0);
    transpose_split<<<gtEE, tb>>>(proj_c_w, bhi, blo, E, E);
    tc_gemm<<<gE, 256, GEMM_SMEM>>>(ahi, alo, bhi, blo, proj_c_b, px1,
                                    px2, nullptr, nullptr, E, E, 0);

    // ---- FFN ----
    ln_split<<<M, 256>>>(px2, ln3_g, ln3_b, ahi, alo);
    transpose_split<<<gtE4, tb>>>(w1, bhi, blo, E, 4 * E);
    tc_gemm<<<g4E, 256, GEMM_SMEM>>>(ahi, alo, bhi, blo, b1, nullptr,
                                     nullptr, fhi, flo, 4 * E, E, 1);
    transpose_split<<<gt4E, tb>>>(w2, bhi, blo, 4 * E, E);
    tc_gemm<<<gE, 256, GEMM_SMEM>>>(fhi, flo, bhi, blo, b2, px2,
                                    out, nullptr, nullptr, E, 4 * E, 0);
}

// round 5
// speedup vs baseline: 2.7078x; 1.5778x over previous
#include <cuda_runtime.h>
#include <cuda_bf16.h>
#include <math.h>
#include <stdint.h>

// ---------------------------------------------------------------------------
// DecoderLayerWithContext — Round 5 (Round-4 resubmit + P-fragment fix)
// Dense GEMMs: HMMA mma.sync bf16x3 (validated R3).
// Attention: fused flash-attention (HMMA QK^T + online softmax + HMMA PV).
// Fix vs R4: removed erroneous ph[1]<->ph[2] swap — C-frag of adjacent n8
// tiles maps identically to the A-frag (a1=row+8/k-lo, a2=row/k-hi).
// ---------------------------------------------------------------------------

namespace cfg {
constexpr int E  = 1024;
constexpr int NH = 16;
constexpr int HD = 64;
constexpr int B  = 2;
constexpr int T  = 2048;
constexpr int S  = 2048;
constexpr int BH = B * NH;
constexpr float SCALE = 0.03125f;                 // 1/sqrt(1024)
constexpr float SC2   = 0.03125f * 1.44269504f;   // SCALE * log2(e)
}

// -------------------------- device scratch ---------------------------------
__device__ float g_x1 [cfg::B * cfg::T * cfg::E];
__device__ float g_x2 [cfg::B * cfg::T * cfg::E];
__device__ uint16_t g_ahi[(size_t)16 * 1024 * 1024];  // act [0,4M), ctx [8M,12M)
__device__ uint16_t g_alo[(size_t)16 * 1024 * 1024];
__device__ uint16_t g_bhi[(size_t)4 * 1024 * 1024];
__device__ uint16_t g_blo[(size_t)4 * 1024 * 1024];
__device__ uint16_t g_qhi[(size_t)4 * 1024 * 1024];
__device__ uint16_t g_qlo[(size_t)4 * 1024 * 1024];
__device__ uint16_t g_khi[(size_t)4 * 1024 * 1024];
__device__ uint16_t g_klo[(size_t)4 * 1024 * 1024];
__device__ uint16_t g_vhi[(size_t)4 * 1024 * 1024];
__device__ uint16_t g_vlo[(size_t)4 * 1024 * 1024];
__device__ uint16_t g_fhi[(size_t)16 * 1024 * 1024];
__device__ uint16_t g_flo[(size_t)16 * 1024 * 1024];

// -------------------------- asm helpers ------------------------------------
__device__ __forceinline__ uint32_t smem_u32(const void* p) {
    uint32_t a;
    asm("{ .reg .u64 t; cvta.to.shared.u64 t, %1; cvt.u32.u64 %0, t; }" : "=r"(a) : "l"(p));
    return a;
}
#define CP16(s, g) \
    asm volatile("cp.async.cg.shared.global [%0], [%1], 16;" :: "r"(s), "l"(g))
#define CP_COMMIT()  asm volatile("cp.async.commit_group;" ::: "memory")
#define CP_WAIT0()   asm volatile("cp.async.wait_group 0;" ::: "memory")
#define CP_WAIT1()   asm volatile("cp.async.wait_group 1;" ::: "memory")

#define LDSM4(r, addr)                                                        \
    asm volatile("ldmatrix.sync.aligned.m8n8.x4.shared.b16 {%0,%1,%2,%3}, [%4];" \
        : "=r"((r)[0]), "=r"((r)[1]), "=r"((r)[2]), "=r"((r)[3]) : "r"(addr))
#define LDSM4T(r, addr)                                                       \
    asm volatile("ldmatrix.sync.aligned.m8n8.x4.trans.shared.b16 {%0,%1,%2,%3}, [%4];" \
        : "=r"((r)[0]), "=r"((r)[1]), "=r"((r)[2]), "=r"((r)[3]) : "r"(addr))

#define MMA16816(d, a, b0, b1)                                                \
    asm volatile("mma.sync.aligned.m16n8k16.row.col.f32.bf16.bf16.f32 "       \
        "{%0,%1,%2,%3},{%4,%5,%6,%7},{%8,%9},{%0,%1,%2,%3};"                  \
        : "+f"((d)[0]), "+f"((d)[1]), "+f"((d)[2]), "+f"((d)[3])              \
        : "r"((a)[0]), "r"((a)[1]), "r"((a)[2]), "r"((a)[3]), "r"(b0), "r"(b1))

// pack two fp32 -> bf16x2 (lower = p0, upper = p1)
#define CVTPK(d, p1, p0) \
    asm("cvt.rn.bf16x2.f32 %0, %1, %2;" : "=r"(d) : "f"(p1), "f"(p0))

__device__ __forceinline__ void bsplit(float x, unsigned short& h, unsigned short& l) {
    __nv_bfloat16 hb = __float2bfloat16(x);
    __nv_bfloat16 lb = __float2bfloat16(x - __bfloat162float(hb));
    h = *reinterpret_cast<unsigned short*>(&hb);
    l = *reinterpret_cast<unsigned short*>(&lb);
}
__device__ __forceinline__ float gelu_f(float x) {
    return 0.5f * x * (1.0f + erff(x * 0.7071067811865475f));
}

// SMEM stage layout for tc_gemm: Ah | Al | Bh | Bl (16 KB each)
constexpr int OFF_AH = 0;
constexpr int OFF_AL = 16384;
constexpr int OFF_BH = 32768;
constexpr int OFF_BL = 49152;
constexpr int STAGE_BYTES = 65536;

// ---------------------------------------------------------------------------
// HMMA GEMM (validated R3): C[M,N](+epi) = A[M,K]*B[N,K]^T, bf16x3.
// ---------------------------------------------------------------------------
__global__ void __launch_bounds__(256, 1)
tc_gemm(const uint16_t* __restrict__ Ahi, const uint16_t* __restrict__ Alo,
        const uint16_t* __restrict__ Bhi, const uint16_t* __restrict__ Blo,
        const float* __restrict__ bias, const float* __restrict__ res,
        float* __restrict__ C, uint16_t* __restrict__ Chi, uint16_t* __restrict__ Clo,
        int N, int K, int do_gelu) {
    extern __shared__ uint8_t dsm[];
    uint8_t* tiles = (uint8_t*)(((uintptr_t)dsm + 1023) & ~(uintptr_t)1023);
    const uint32_t tb = smem_u32(tiles);

    const int tid  = threadIdx.x;
    const int lane = tid & 31;
    const int wid  = tid >> 5;
    const int wr   = wid >> 2;
    const int wc   = wid & 3;
    const int row0 = blockIdx.y * 128;
    const int col0 = blockIdx.x * 128;

    const int lrow = tid >> 1, lhalf = tid & 1;
    uint32_t so[4];
#pragma unroll
    for (int i = 0; i < 4; i++) {
        uint32_t o = (uint32_t)lrow * 128 + (uint32_t)lhalf * 64 + i * 16;
        so[i] = o ^ ((o >> 3) & 0x70);
    }
    const size_t a_base = (size_t)(row0 + lrow) * K + lhalf * 32;
    const size_t b_base = (size_t)(col0 + lrow) * K + lhalf * 32;

    const int ka = (lane >> 4) * 16;
    const int kb = ((lane >> 3) & 1) * 16;
    uint32_t aoff[4], xA[4];
#pragma unroll
    for (int mt = 0; mt < 4; mt++) {
        int r = wr * 64 + mt * 16 + (lane & 15);
        aoff[mt] = (uint32_t)r * 128;
        xA[mt] = (uint32_t)(r & 7) * 16;
    }
    uint32_t boff[2], xB[2];
#pragma unroll
    for (int p = 0; p < 2; p++) {
        int r = wc * 32 + p * 16 + ((lane >> 4) & 1) * 8 + (lane & 7);
        boff[p] = (uint32_t)r * 128;
        xB[p] = (uint32_t)(r & 7) * 16;
    }

    float acc[4][4][4];
#pragma unroll
    for (int mt = 0; mt < 4; mt++)
#pragma unroll
        for (int nt = 0; nt < 4; nt++)
#pragma unroll
            for (int e = 0; e < 4; e++) acc[mt][nt][e] = 0.0f;

    const int NC = K >> 6;
    {
        const uint32_t st = tb;
#pragma unroll
        for (int i = 0; i < 4; i++) {
            CP16(st + OFF_AH + so[i], Ahi + a_base + i * 8);
            CP16(st + OFF_AL + so[i], Alo + a_base + i * 8);
            CP16(st + OFF_BH + so[i], Bhi + b_base + i * 8);
            CP16(st + OFF_BL + so[i], Blo + b_base + i * 8);
        }
        CP_COMMIT();
    }

    for (int c = 0; c < NC; c++) {
        if (c + 1 < NC) {
            const uint32_t st = tb + ((c + 1) & 1) * STAGE_BYTES;
            const int kc = (c + 1) << 6;
#pragma unroll
            for (int i = 0; i < 4; i++) {
                CP16(st + OFF_AH + so[i], Ahi + a_base + kc + i * 8);
                CP16(st + OFF_AL + so[i], Alo + a_base + kc + i * 8);
                CP16(st + OFF_BH + so[i], Bhi + b_base + kc + i * 8);
                CP16(st + OFF_BL + so[i], Blo + b_base + kc + i * 8);
            }
            CP_COMMIT();
            CP_WAIT1();
        } else {
            CP_WAIT0();
        }
        __syncthreads();

        const uint32_t sb = tb + (c & 1) * STAGE_BYTES;
#pragma unroll
        for (int ks = 0; ks < 4; ks++) {
            uint32_t ah[4][4], al[4][4], bh[2][4], bl[2][4];
            const uint32_t cba = (uint32_t)(ks * 32 + ka);
#pragma unroll
            for (int mt = 0; mt < 4; mt++) {
                const uint32_t off = aoff[mt] + (cba ^ xA[mt]);
                LDSM4(ah[mt], sb + OFF_AH + off);
                LDSM4(al[mt], sb + OFF_AL + off);
            }
            const uint32_t cbb = (uint32_t)(ks * 32 + kb);
#pragma unroll
            for (int p = 0; p < 2; p++) {
                const uint32_t off = boff[p] + (cbb ^ xB[p]);
                LDSM4(bh[p], sb + OFF_BH + off);
                LDSM4(bl[p], sb + OFF_BL + off);
            }
#pragma unroll
            for (int mt = 0; mt < 4; mt++)
#pragma unroll
                for (int nt = 0; nt < 4; nt++) {
                    const int p = nt >> 1, q = (nt & 1) * 2;
                    MMA16816(acc[mt][nt], ah[mt], bh[p][q], bh[p][q + 1]);
                    MMA16816(acc[mt][nt], ah[mt], bl[p][q], bl[p][q + 1]);
                    MMA16816(acc[mt][nt], al[mt], bh[p][q], bh[p][q + 1]);
                }
        }
        __syncthreads();
    }

    const int mrow = lane >> 2;
    const int ncol = (lane & 3) * 2;
#pragma unroll
    for (int mt = 0; mt < 4; mt++) {
#pragma unroll
        for (int half = 0; half < 2; half++) {
            const int r = row0 + wr * 64 + mt * 16 + mrow + half * 8;
#pragma unroll
            for (int nt = 0; nt < 4; nt++) {
                float v0 = acc[mt][nt][half * 2 + 0];
                float v1 = acc[mt][nt][half * 2 + 1];
                const int cc = col0 + wc * 32 + nt * 8 + ncol;
                if (bias) { v0 += bias[cc]; v1 += bias[cc + 1]; }
                if (do_gelu) { v0 = gelu_f(v0); v1 = gelu_f(v1); }
                if (res) {
                    v0 += res[(size_t)r * N + cc];
                    v1 += res[(size_t)r * N + cc + 1];
                }
                if (C) *(float2*)(C + (size_t)r * N + cc) = make_float2(v0, v1);
                if (Chi) {
                    unsigned short h0, l0, h1, l1;
                    bsplit(v0, h0, l0);
                    bsplit(v1, h1, l1);
                    *(uint32_t*)(Chi + (size_t)r * N + cc) = (uint32_t)h0 | ((uint32_t)h1 << 16);
                    *(uint32_t*)(Clo + (size_t)r * N + cc) = (uint32_t)l0 | ((uint32_t)l1 << 16);
                }
            }
        }
    }
}

// ---------------------------------------------------------------------------
// Fused flash attention. 128 q-rows per CTA; 8 warps own 16 rows each.
// Q,K,V bf16 hi/lo (x3 MMAs). Online softmax in base-2. Output bf16 hi/lo.
// grid (Tq/128, BH), block 256, smem 32KB(Q) + 2*64KB(KV).
// ---------------------------------------------------------------------------
constexpr int FQ_H = 0;
constexpr int FQ_L = 16384;
constexpr int FKV0 = 32768;
constexpr int FK_H = 0, FK_L = 16384, FV_H = 32768, FV_L = 49152;
constexpr int FSTG = 65536;
constexpr int FLASH_SMEM = 32768 + 2 * FSTG + 1024;

__global__ void __launch_bounds__(256, 1)
flash_attn(const uint16_t* __restrict__ Qhi, const uint16_t* __restrict__ Qlo,
           const uint16_t* __restrict__ Khi, const uint16_t* __restrict__ Klo,
           const uint16_t* __restrict__ Vhi, const uint16_t* __restrict__ Vlo,
           uint16_t* __restrict__ Ohi, uint16_t* __restrict__ Olo,
           int Tq, int Tk, int causal) {
    extern __shared__ uint8_t dsm[];
    uint8_t* basep = (uint8_t*)(((uintptr_t)dsm + 1023) & ~(uintptr_t)1023);
    const uint32_t tb = smem_u32(basep);

    const int bh = blockIdx.y;
    const int b = bh >> 4, h = bh & 15;
    int it = blockIdx.x;
    if (causal) it = (int)gridDim.x - 1 - it;     // big tiles first
    const int i0 = it * 128;
    const int NJ = causal ? (it + 1) : (Tk >> 7);

    const int tid = threadIdx.x;
    const int lane = tid & 31;
    const int wid = tid >> 5;

    // ---- cp.async geometry ----
    const int lrow = tid >> 1, lhalf = tid & 1;
    uint32_t so[4];
#pragma unroll
    for (int i = 0; i < 4; i++) {
        uint32_t o = (uint32_t)lrow * 128 + (uint32_t)lhalf * 64 + i * 16;
        so[i] = o ^ ((o >> 3) & 0x70);
    }
    const size_t qg = (size_t)(b * Tq + i0 + lrow) * cfg::E + h * cfg::HD + lhalf * 32;
    const size_t kg = (size_t)(b * Tk + lrow) * cfg::E + h * cfg::HD + lhalf * 32;

#pragma unroll
    for (int i = 0; i < 4; i++) {
        CP16(tb + FQ_H + so[i], Qhi + qg + i * 8);
        CP16(tb + FQ_L + so[i], Qlo + qg + i * 8);
    }
    {
        const uint32_t st = tb + FKV0;
#pragma unroll
        for (int i = 0; i < 4; i++) {
            CP16(st + FK_H + so[i], Khi + kg + i * 8);
            CP16(st + FK_L + so[i], Klo + kg + i * 8);
            CP16(st + FV_H + so[i], Vhi + kg + i * 8);
            CP16(st + FV_L + so[i], Vlo + kg + i * 8);
        }
    }
    CP_COMMIT();

    // ---- fragment geometry ----
    const int arow = wid * 16 + (lane & 15);
    const uint32_t aoff = (uint32_t)arow * 128;
    const uint32_t axr  = (uint32_t)(arow & 7) * 16;
    const int ka = (lane >> 4) * 16;
    const int nrow_b = ((lane >> 4) & 1) * 8 + (lane & 7);   // K (B, non-trans)
    const int kb = ((lane >> 3) & 1) * 16;
    const int vm = lane >> 3;                                // V (B, trans)
    const int vrow_b = (vm & 1) * 8 + (lane & 7);
    const int vcol_b = (vm >> 1) * 16;

    uint32_t qh[4][4], ql[4][4];
    float accO[8][4];
#pragma unroll
    for (int nt = 0; nt < 8; nt++)
#pragma unroll
        for (int e = 0; e < 4; e++) accO[nt][e] = 0.0f;
    float m2[2] = {-3.0e38f, -3.0e38f};
    float lsum[2] = {0.0f, 0.0f};

    const int mrow = lane >> 2;
    const int cb = (lane & 3) * 2;
    const int irow0 = i0 + wid * 16 + mrow;
    const int irow1 = irow0 + 8;

    for (int jt = 0; jt < NJ; jt++) {
        if (jt + 1 < NJ) {
            const uint32_t st = tb + FKV0 + ((jt + 1) & 1) * FSTG;
            const size_t kgj = kg + (size_t)(jt + 1) * 128 * cfg::E;
#pragma unroll
            for (int i = 0; i < 4; i++) {
                CP16(st + FK_H + so[i], Khi + kgj + i * 8);
                CP16(st + FK_L + so[i], Klo + kgj + i * 8);
                CP16(st + FV_H + so[i], Vhi + kgj + i * 8);
                CP16(st + FV_L + so[i], Vlo + kgj + i * 8);
            }
            CP_COMMIT();
            CP_WAIT1();
        } else {
            CP_WAIT0();
        }
        __syncthreads();

        if (jt == 0) {
#pragma unroll
            for (int ks = 0; ks < 4; ks++) {
                const uint32_t off = aoff + (((uint32_t)(ks * 32 + ka)) ^ axr);
                LDSM4(qh[ks], tb + FQ_H + off);
                LDSM4(ql[ks], tb + FQ_L + off);
            }
        }
        const uint32_t sb = tb + FKV0 + (jt & 1) * FSTG;

        // ---- S = Q K^T (bf16x3) ----
        float accS[16][4];
#pragma unroll
        for (int nt = 0; nt < 16; nt++)
#pragma unroll
            for (int e = 0; e < 4; e++) accS[nt][e] = 0.0f;

#pragma unroll
        for (int ks = 0; ks < 4; ks++) {
            const uint32_t cbb = (uint32_t)(ks * 32 + kb);
#pragma unroll
            for (int ntp = 0; ntp < 8; ntp++) {
                const int r = ntp * 16 + nrow_b;
                const uint32_t off = (uint32_t)r * 128 + (cbb ^ ((uint32_t)(r & 7) * 16));
                uint32_t bh4[4], bl4[4];
                LDSM4(bh4, sb + FK_H + off);
                LDSM4(bl4, sb + FK_L + off);
                MMA16816(accS[2 * ntp],     qh[ks], bh4[0], bh4[1]);
                MMA16816(accS[2 * ntp],     qh[ks], bl4[0], bl4[1]);
                MMA16816(accS[2 * ntp],     ql[ks], bh4[0], bh4[1]);
                MMA16816(accS[2 * ntp + 1], qh[ks], bh4[2], bh4[3]);
                MMA16816(accS[2 * ntp + 1], qh[ks], bl4[2], bl4[3]);
                MMA16816(accS[2 * ntp + 1], ql[ks], bh4[2], bh4[3]);
            }
        }

        // ---- scale (+ causal mask on diagonal tile) ----
        const int j0 = jt * 128;
        const bool maskTile = causal && (jt == NJ - 1);
#pragma unroll
        for (int nt = 0; nt < 16; nt++)
#pragma unroll
            for (int e = 0; e < 4; e++) accS[nt][e] *= cfg::SC2;
        if (maskTile) {
#pragma unroll
            for (int nt = 0; nt < 16; nt++) {
                const int jc = j0 + nt * 8 + cb;
                if (jc     > irow0) accS[nt][0] = -3.0e38f;
                if (jc + 1 > irow0) accS[nt][1] = -3.0e38f;
                if (jc     > irow1) accS[nt][2] = -3.0e38f;
                if (jc + 1 > irow1) accS[nt][3] = -3.0e38f;
            }
        }

        // ---- online softmax (quad-local) ----
        float mx0 = -3.0e38f, mx1 = -3.0e38f;
#pragma unroll
        for (int nt = 0; nt < 16; nt++) {
            mx0 = fmaxf(mx0, fmaxf(accS[nt][0], accS[nt][1]));
            mx1 = fmaxf(mx1, fmaxf(accS[nt][2], accS[nt][3]));
        }
        mx0 = fmaxf(mx0, __shfl_xor_sync(0xffffffffu, mx0, 1));
        mx0 = fmaxf(mx0, __shfl_xor_sync(0xffffffffu, mx0, 2));
        mx1 = fmaxf(mx1, __shfl_xor_sync(0xffffffffu, mx1, 1));
        mx1 = fmaxf(mx1, __shfl_xor_sync(0xffffffffu, mx1, 2));
        const float mn0 = fmaxf(m2[0], mx0);
        const float mn1 = fmaxf(m2[1], mx1);
        const float al0 = exp2f(m2[0] - mn0);
        const float al1 = exp2f(m2[1] - mn1);
        m2[0] = mn0; m2[1] = mn1;

        float s0 = 0.0f, s1 = 0.0f;
#pragma unroll
        for (int nt = 0; nt < 16; nt++) {
            float p0 = exp2f(accS[nt][0] - mn0);
            float p1 = exp2f(accS[nt][1] - mn0);
            float p2 = exp2f(accS[nt][2] - mn1);
            float p3 = exp2f(accS[nt][3] - mn1);
            accS[nt][0] = p0; accS[nt][1] = p1;
            accS[nt][2] = p2; accS[nt][3] = p3;
            s0 += p0 + p1;
            s1 += p2 + p3;
        }
        s0 += __shfl_xor_sync(0xffffffffu, s0, 1);
        s0 += __shfl_xor_sync(0xffffffffu, s0, 2);
        s1 += __shfl_xor_sync(0xffffffffu, s1, 1);
        s1 += __shfl_xor_sync(0xffffffffu, s1, 2);
        lsum[0] = lsum[0] * al0 + s0;
        lsum[1] = lsum[1] * al1 + s1;

#pragma unroll
        for (int nt = 0; nt < 8; nt++) {
            accO[nt][0] *= al0; accO[nt][1] *= al0;
            accO[nt][2] *= al1; accO[nt][3] *= al1;
        }

        // ---- O += P V (bf16x3, P split in registers; C-frag == A-frag) ----
#pragma unroll
        for (int ks = 0; ks < 8; ks++) {
            uint32_t ph[4], pl[4];
#pragma unroll
            for (int q = 0; q < 2; q++) {
                const float p0 = accS[2 * ks + q][0];
                const float p1 = accS[2 * ks + q][1];
                const float p2 = accS[2 * ks + q][2];
                const float p3 = accS[2 * ks + q][3];
                uint32_t h01, h23;
                CVTPK(h01, p1, p0);
                CVTPK(h23, p3, p2);
                ph[2 * q]     = h01;   // a0/a2: row,   k-lo/k-hi
                ph[2 * q + 1] = h23;   // a1/a3: row+8, k-lo/k-hi
                const float l0 = p0 - __uint_as_float(h01 << 16);
                const float l1 = p1 - __uint_as_float(h01 & 0xFFFF0000u);
                const float l2 = p2 - __uint_as_float(h23 << 16);
                const float l3 = p3 - __uint_as_float(h23 & 0xFFFF0000u);
                uint32_t u01, u23;
                CVTPK(u01, l1, l0);
                CVTPK(u23, l3, l2);
                pl[2 * q]     = u01;
                pl[2 * q + 1] = u23;
            }
            const int jr = ks * 16 + vrow_b;
            const uint32_t roff = (uint32_t)jr * 128;
            const uint32_t xr = (uint32_t)(jr & 7) * 16;
#pragma unroll
            for (int ntp = 0; ntp < 4; ntp++) {
                const uint32_t off = roff + (((uint32_t)(ntp * 32 + vcol_b)) ^ xr);
                uint32_t vh4[4], vl4[4];
                LDSM4T(vh4, sb + FV_H + off);
                LDSM4T(vl4, sb + FV_L + off);
                MMA16816(accO[2 * ntp],     ph, vh4[0], vh4[1]);
                MMA16816(accO[2 * ntp],     ph, vl4[0], vl4[1]);
                MMA16816(accO[2 * ntp],     pl, vh4[0], vh4[1]);
                MMA16816(accO[2 * ntp + 1], ph, vh4[2], vh4[3]);
                MMA16816(accO[2 * ntp + 1], ph, vl4[2], vl4[3]);
                MMA16816(accO[2 * ntp + 1], pl, vh4[2], vh4[3]);
            }
        }
        __syncthreads();
    }

    // ---- epilogue ----
    const float li0 = 1.0f / lsum[0];
    const float li1 = 1.0f / lsum[1];
#pragma unroll
    for (int nt = 0; nt < 8; nt++) {
        const float v0 = accO[nt][0] * li0;
        const float v1 = accO[nt][1] * li0;
        const float v2 = accO[nt][2] * li1;
        const float v3 = accO[nt][3] * li1;
        unsigned short h0, l0, h1, l1, h2, l2, h3, l3;
        bsplit(v0, h0, l0); bsplit(v1, h1, l1);
        bsplit(v2, h2, l2); bsplit(v3, h3, l3);
        const int d = h * cfg::HD + nt * 8 + cb;
        const size_t o0 = (size_t)(b * Tq + irow0) * cfg::E + d;
        const size_t o1 = (size_t)(b * Tq + irow1) * cfg::E + d;
        *(uint32_t*)(Ohi + o0) = (uint32_t)h0 | ((uint32_t)h1 << 16);
        *(uint32_t*)(Olo + o0) = (uint32_t)l0 | ((uint32_t)l1 << 16);
        *(uint32_t*)(Ohi + o1) = (uint32_t)h2 | ((uint32_t)h3 << 16);
        *(uint32_t*)(Olo + o1) = (uint32_t)l2 | ((uint32_t)l3 << 16);
    }
}

// ---------------------------------------------------------------------------
// LayerNorm emitting bf16 hi/lo split directly
// ---------------------------------------------------------------------------
__global__ void ln_split(const float* __restrict__ X, const float* __restrict__ gam,
                         const float* __restrict__ bet, uint16_t* __restrict__ Hi,
                         uint16_t* __restrict__ Lo) {
    __shared__ float red[256];
    const int row = blockIdx.x;
    const int tid = threadIdx.x;
    const float4 v = ((const float4*)(X + (size_t)row * cfg::E))[tid];

    float s = v.x + v.y + v.z + v.w;
    red[tid] = s; __syncthreads();
    for (int off = 128; off; off >>= 1) {
        if (tid < off) red[tid] += red[tid + off];
        __syncthreads();
    }
    const float mu = red[0] * (1.0f / cfg::E);
    __syncthreads();

    const float dx = v.x - mu, dy = v.y - mu, dz = v.z - mu, dw = v.w - mu;
    red[tid] = dx*dx + dy*dy + dz*dz + dw*dw; __syncthreads();
    for (int off = 128; off; off >>= 1) {
        if (tid < off) red[tid] += red[tid + off];
        __syncthreads();
    }
    const float var = red[0] * (1.0f / cfg::E);
    const float r = rsqrtf(var + 1e-5f);

    const float4 g4 = ((const float4*)gam)[tid];
    const float4 b4 = ((const float4*)bet)[tid];
    float o[4];
    o[0] = dx * r * g4.x + b4.x;
    o[1] = dy * r * g4.y + b4.y;
    o[2] = dz * r * g4.z + b4.z;
    o[3] = dw * r * g4.w + b4.w;
    ushort4 ho, lo;
    unsigned short hs[4], ls[4];
#pragma unroll
    for (int c = 0; c < 4; c++) bsplit(o[c], hs[c], ls[c]);
    ho.x = hs[0]; ho.y = hs[1]; ho.z = hs[2]; ho.w = hs[3];
    lo.x = ls[0]; lo.y = ls[1]; lo.z = ls[2]; lo.w = ls[3];
    ((ushort4*)(Hi + (size_t)row * cfg::E))[tid] = ho;
    ((ushort4*)(Lo + (size_t)row * cfg::E))[tid] = lo;
}

__global__ void split_f32(const float* __restrict__ X, uint16_t* __restrict__ Hi,
                          uint16_t* __restrict__ Lo, int n4) {
    const int i = blockIdx.x * 256 + threadIdx.x;
    if (i >= n4) return;
    const float4 v = ((const float4*)X)[i];
    float xs[4] = {v.x, v.y, v.z, v.w};
    unsigned short hs[4], ls[4];
#pragma unroll
    for (int c = 0; c < 4; c++) bsplit(xs[c], hs[c], ls[c]);
    ushort4 ho, lo;
    ho.x = hs[0]; ho.y = hs[1]; ho.z = hs[2]; ho.w = hs[3];
    lo.x = ls[0]; lo.y = ls[1]; lo.z = ls[2]; lo.w = ls[3];
    ((ushort4*)Hi)[i] = ho;
    ((ushort4*)Lo)[i] = lo;
}

__global__ void transpose_split(const float* __restrict__ W, uint16_t* __restrict__ Hi,
                                uint16_t* __restrict__ Lo, int Kd, int Nd) {
    __shared__ float tile[32][33];
    const int n0 = blockIdx.x * 32, k0 = blockIdx.y * 32;
    const int tx = threadIdx.x, ty = threadIdx.y;
    for (int r = ty; r < 32; r += 8)
        tile[r][tx] = W[(size_t)(k0 + r) * Nd + n0 + tx];
    __syncthreads();
    for (int r = ty; r < 32; r += 8) {
        const float x = tile[tx][r];
        unsigned short h, l;
        bsplit(x, h, l);
        const size_t o = (size_t)(n0 + r) * Kd + k0 + tx;
        Hi[o] = h;
        Lo[o] = l;
    }
}

// ---------------------------------------------------------------------------
// Launch sequence
// ---------------------------------------------------------------------------
extern "C" void kernel_launch(void* const* d_in, const int* in_sizes, int n_in,
                              void* d_out, int out_size) {
    using namespace cfg;
    const float* x        = (const float*)d_in[0];
    const float* context  = (const float*)d_in[1];
    const float* ln1_g    = (const float*)d_in[2];
    const float* ln1_b    = (const float*)d_in[3];
    const float* ln2_g    = (const float*)d_in[4];
    const float* ln2_b    = (const float*)d_in[5];
    const float* ln3_g    = (const float*)d_in[6];
    const float* ln3_b    = (const float*)d_in[7];
    const float* Wq_s     = (const float*)d_in[8];
    const float* Wk_s     = (const float*)d_in[9];
    const float* Wv_s     = (const float*)d_in[10];
    const float* proj_s_w = (const float*)d_in[11];
    const float* proj_s_b = (const float*)d_in[12];
    const float* Wq_c     = (const float*)d_in[13];
    const float* Wk_c     = (const float*)d_in[14];
    const float* Wv_c     = (const float*)d_in[15];
    const float* proj_c_w = (const float*)d_in[16];
    const float* proj_c_b = (const float*)d_in[17];
    const float* w1       = (const float*)d_in[18];
    const float* b1       = (const float*)d_in[19];
    const float* w2       = (const float*)d_in[20];
    const float* b2       = (const float*)d_in[21];
    float* out = (float*)d_out;

    float *px1, *px2;
    uint16_t *ahi, *alo, *bhi, *blo, *qhi, *qlo, *khi, *klo, *vhi, *vlo, *fhi, *flo;
    cudaGetSymbolAddress((void**)&px1, g_x1);
    cudaGetSymbolAddress((void**)&px2, g_x2);
    cudaGetSymbolAddress((void**)&ahi, g_ahi);
    cudaGetSymbolAddress((void**)&alo, g_alo);
    cudaGetSymbolAddress((void**)&bhi, g_bhi);
    cudaGetSymbolAddress((void**)&blo, g_blo);
    cudaGetSymbolAddress((void**)&qhi, g_qhi);
    cudaGetSymbolAddress((void**)&qlo, g_qlo);
    cudaGetSymbolAddress((void**)&khi, g_khi);
    cudaGetSymbolAddress((void**)&klo, g_klo);
    cudaGetSymbolAddress((void**)&vhi, g_vhi);
    cudaGetSymbolAddress((void**)&vlo, g_vlo);
    cudaGetSymbolAddress((void**)&fhi, g_fhi);
    cudaGetSymbolAddress((void**)&flo, g_flo);
    uint16_t* chi = ahi + (size_t)8 * 1024 * 1024;
    uint16_t* clo = alo + (size_t)8 * 1024 * 1024;

    const int GEMM_SMEM = 2 * STAGE_BYTES + 1024;
    cudaFuncSetAttribute(tc_gemm, cudaFuncAttributeMaxDynamicSharedMemorySize, GEMM_SMEM);
    cudaFuncSetAttribute(flash_attn, cudaFuncAttributeMaxDynamicSharedMemorySize, FLASH_SMEM);

    const int M = B * T;
    const dim3 gE  (E / 128,     M / 128);
    const dim3 g4E (4 * E / 128, M / 128);
    const dim3 gfl (T / 128, BH);
    const int nME4 = (M * E) / 4;
    const dim3 gtEE (E / 32, E / 32);
    const dim3 gtE4 (4 * E / 32, E / 32);
    const dim3 gt4E (E / 32, 4 * E / 32);
    const dim3 tbt(32, 8);

    // ---- self attention (causal) ----
    ln_split<<<M, 256>>>(x, ln1_g, ln1_b, ahi, alo);
    transpose_split<<<gtEE, tbt>>>(Wq_s, bhi, blo, E, E);
    tc_gemm<<<gE, 256, GEMM_SMEM>>>(ahi, alo, bhi, blo, nullptr, nullptr,
                                    nullptr, qhi, qlo, E, E, 0);
    transpose_split<<<gtEE, tbt>>>(Wk_s, bhi, blo, E, E);
    tc_gemm<<<gE, 256, GEMM_SMEM>>>(ahi, alo, bhi, blo, nullptr, nullptr,
                                    nullptr, khi, klo, E, E, 0);
    transpose_split<<<gtEE, tbt>>>(Wv_s, bhi, blo, E, E);
    tc_gemm<<<gE, 256, GEMM_SMEM>>>(ahi, alo, bhi, blo, nullptr, nullptr,
                                    nullptr, vhi, vlo, E, E, 0);
    flash_attn<<<gfl, 256, FLASH_SMEM>>>(qhi, qlo, khi, klo, vhi, vlo,
                                         ahi, alo, T, S, 1);
    transpose_split<<<gtEE, tbt>>>(proj_s_w, bhi, blo, E, E);
    tc_gemm<<<gE, 256, GEMM_SMEM>>>(ahi, alo, bhi, blo, proj_s_b, x,
                                    px1, nullptr, nullptr, E, E, 0);

    // ---- cross attention (context NOT normalized) ----
    ln_split<<<M, 256>>>(px1, ln2_g, ln2_b, ahi, alo);
    transpose_split<<<gtEE, tbt>>>(Wq_c, bhi, blo, E, E);
    tc_gemm<<<gE, 256, GEMM_SMEM>>>(ahi, alo, bhi, blo, nullptr, nullptr,
                                    nullptr, qhi, qlo, E, E, 0);
    split_f32<<<(nME4 + 255) / 256, 256>>>(context, chi, clo, nME4);
    transpose_split<<<gtEE, tbt>>>(Wk_c, bhi, blo, E, E);
    tc_gemm<<<gE, 256, GEMM_SMEM>>>(chi, clo, bhi, blo, nullptr, nullptr,
                                    nullptr, khi, klo, E, E, 0);
    transpose_split<<<gtEE, tbt>>>(Wv_c, bhi, blo, E, E);
    tc_gemm<<<gE, 256, GEMM_SMEM>>>(chi, clo, bhi, blo, nullptr, nullptr,
                                    nullptr, vhi, vlo, E, E, 0);
    flash_attn<<<gfl, 256, FLASH_SMEM>>>(qhi, qlo, khi, klo, vhi, vlo,
                                         ahi, alo, T, S, 0);
    transpose_split<<<gtEE, tbt>>>(proj_c_w, bhi, blo, E, E);
    tc_gemm<<<gE, 256, GEMM_SMEM>>>(ahi, alo, bhi, blo, proj_c_b, px1,
                                    px2, nullptr, nullptr, E, E, 0);

    // ---- FFN ----
    ln_split<<<M, 256>>>(px2, ln3_g, ln3_b, ahi, alo);
    transpose_split<<<gtE4, tbt>>>(w1, bhi, blo, E, 4 * E);
    tc_gemm<<<g4E, 256, GEMM_SMEM>>>(ahi, alo, bhi, blo, b1, nullptr,
                                     nullptr, fhi, flo, 4 * E, E, 1);
    transpose_split<<<gt4E, tbt>>>(w2, bhi, blo, 4 * E, E);
    tc_gemm<<<gE, 256, GEMM_SMEM>>>(fhi, flo, bhi, blo, b2, px2,
                                    out, nullptr, nullptr, E, 4 * E, 0);
}

// round 6
// speedup vs baseline: 2.7134x; 1.0021x over previous
#include <cuda_runtime.h>
#include <cuda_bf16.h>
#include <math.h>
#include <stdint.h>

// ---------------------------------------------------------------------------
// DecoderLayerWithContext — Round 6
// vs R5: (1) MMA asm non-volatile + term-outer ordering (breaks RAW chains),
// (2) merged QKV GEMM (N=3072) / merged cross-KV GEMM (N=2048) with
//     stride-parametrized flash attention (wave-quantization fix).
// ---------------------------------------------------------------------------

namespace cfg {
constexpr int E  = 1024;
constexpr int NH = 16;
constexpr int HD = 64;
constexpr int B  = 2;
constexpr int T  = 2048;
constexpr int S  = 2048;
constexpr int BH = B * NH;
constexpr float SCALE = 0.03125f;
constexpr float SC2   = 0.03125f * 1.44269504f;
}

// -------------------------- device scratch ---------------------------------
__device__ float g_x1 [cfg::B * cfg::T * cfg::E];
__device__ float g_x2 [cfg::B * cfg::T * cfg::E];
__device__ uint16_t g_ahi[(size_t)16 * 1024 * 1024];  // act [0,4M), ctx [8M,12M)
__device__ uint16_t g_alo[(size_t)16 * 1024 * 1024];
__device__ uint16_t g_bhi[(size_t)4 * 1024 * 1024];
__device__ uint16_t g_blo[(size_t)4 * 1024 * 1024];
__device__ uint16_t g_qhi[(size_t)4 * 1024 * 1024];
__device__ uint16_t g_qlo[(size_t)4 * 1024 * 1024];
__device__ uint16_t g_fhi[(size_t)16 * 1024 * 1024];
__device__ uint16_t g_flo[(size_t)16 * 1024 * 1024];

// -------------------------- asm helpers ------------------------------------
__device__ __forceinline__ uint32_t smem_u32(const void* p) {
    uint32_t a;
    asm("{ .reg .u64 t; cvta.to.shared.u64 t, %1; cvt.u32.u64 %0, t; }" : "=r"(a) : "l"(p));
    return a;
}
#define CP16(s, g) \
    asm volatile("cp.async.cg.shared.global [%0], [%1], 16;" :: "r"(s), "l"(g))
#define CP_COMMIT()  asm volatile("cp.async.commit_group;" ::: "memory")
#define CP_WAIT0()   asm volatile("cp.async.wait_group 0;" ::: "memory")
#define CP_WAIT1()   asm volatile("cp.async.wait_group 1;" ::: "memory")

#define LDSM4(r, addr)                                                        \
    asm volatile("ldmatrix.sync.aligned.m8n8.x4.shared.b16 {%0,%1,%2,%3}, [%4];" \
        : "=r"((r)[0]), "=r"((r)[1]), "=r"((r)[2]), "=r"((r)[3]) : "r"(addr))
#define LDSM4T(r, addr)                                                       \
    asm volatile("ldmatrix.sync.aligned.m8n8.x4.trans.shared.b16 {%0,%1,%2,%3}, [%4];" \
        : "=r"((r)[0]), "=r"((r)[1]), "=r"((r)[2]), "=r"((r)[3]) : "r"(addr))

// non-volatile: register-only, lets ptxas schedule across the unrolled block
#define MMA16816(d, a, b0, b1)                                                \
    asm("mma.sync.aligned.m16n8k16.row.col.f32.bf16.bf16.f32 "                \
        "{%0,%1,%2,%3},{%4,%5,%6,%7},{%8,%9},{%0,%1,%2,%3};"                  \
        : "+f"((d)[0]), "+f"((d)[1]), "+f"((d)[2]), "+f"((d)[3])              \
        : "r"((a)[0]), "r"((a)[1]), "r"((a)[2]), "r"((a)[3]), "r"(b0), "r"(b1))

#define CVTPK(d, p1, p0) \
    asm("cvt.rn.bf16x2.f32 %0, %1, %2;" : "=r"(d) : "f"(p1), "f"(p0))

__device__ __forceinline__ void bsplit(float x, unsigned short& h, unsigned short& l) {
    __nv_bfloat16 hb = __float2bfloat16(x);
    __nv_bfloat16 lb = __float2bfloat16(x - __bfloat162float(hb));
    h = *reinterpret_cast<unsigned short*>(&hb);
    l = *reinterpret_cast<unsigned short*>(&lb);
}
__device__ __forceinline__ float gelu_f(float x) {
    return 0.5f * x * (1.0f + erff(x * 0.7071067811865475f));
}

constexpr int OFF_AH = 0;
constexpr int OFF_AL = 16384;
constexpr int OFF_BH = 32768;
constexpr int OFF_BL = 49152;
constexpr int STAGE_BYTES = 65536;

// ---------------------------------------------------------------------------
// HMMA GEMM: C[M,N](+epi) = A[M,K]*B[N,K]^T, bf16x3, term-outer MMA order.
// ---------------------------------------------------------------------------
__global__ void __launch_bounds__(256, 1)
tc_gemm(const uint16_t* __restrict__ Ahi, const uint16_t* __restrict__ Alo,
        const uint16_t* __restrict__ Bhi, const uint16_t* __restrict__ Blo,
        const float* __restrict__ bias, const float* __restrict__ res,
        float* __restrict__ C, uint16_t* __restrict__ Chi, uint16_t* __restrict__ Clo,
        int N, int K, int do_gelu) {
    extern __shared__ uint8_t dsm[];
    uint8_t* tiles = (uint8_t*)(((uintptr_t)dsm + 1023) & ~(uintptr_t)1023);
    const uint32_t tb = smem_u32(tiles);

    const int tid  = threadIdx.x;
    const int lane = tid & 31;
    const int wid  = tid >> 5;
    const int wr   = wid >> 2;
    const int wc   = wid & 3;
    const int row0 = blockIdx.y * 128;
    const int col0 = blockIdx.x * 128;

    const int lrow = tid >> 1, lhalf = tid & 1;
    uint32_t so[4];
#pragma unroll
    for (int i = 0; i < 4; i++) {
        uint32_t o = (uint32_t)lrow * 128 + (uint32_t)lhalf * 64 + i * 16;
        so[i] = o ^ ((o >> 3) & 0x70);
    }
    const size_t a_base = (size_t)(row0 + lrow) * K + lhalf * 32;
    const size_t b_base = (size_t)(col0 + lrow) * K + lhalf * 32;

    const int ka = (lane >> 4) * 16;
    const int kb = ((lane >> 3) & 1) * 16;
    uint32_t aoff[4], xA[4];
#pragma unroll
    for (int mt = 0; mt < 4; mt++) {
        int r = wr * 64 + mt * 16 + (lane & 15);
        aoff[mt] = (uint32_t)r * 128;
        xA[mt] = (uint32_t)(r & 7) * 16;
    }
    uint32_t boff[2], xB[2];
#pragma unroll
    for (int p = 0; p < 2; p++) {
        int r = wc * 32 + p * 16 + ((lane >> 4) & 1) * 8 + (lane & 7);
        boff[p] = (uint32_t)r * 128;
        xB[p] = (uint32_t)(r & 7) * 16;
    }

    float acc[4][4][4];
#pragma unroll
    for (int mt = 0; mt < 4; mt++)
#pragma unroll
        for (int nt = 0; nt < 4; nt++)
#pragma unroll
            for (int e = 0; e < 4; e++) acc[mt][nt][e] = 0.0f;

    const int NC = K >> 6;
    {
        const uint32_t st = tb;
#pragma unroll
        for (int i = 0; i < 4; i++) {
            CP16(st + OFF_AH + so[i], Ahi + a_base + i * 8);
            CP16(st + OFF_AL + so[i], Alo + a_base + i * 8);
            CP16(st + OFF_BH + so[i], Bhi + b_base + i * 8);
            CP16(st + OFF_BL + so[i], Blo + b_base + i * 8);
        }
        CP_COMMIT();
    }

    for (int c = 0; c < NC; c++) {
        if (c + 1 < NC) {
            const uint32_t st = tb + ((c + 1) & 1) * STAGE_BYTES;
            const int kc = (c + 1) << 6;
#pragma unroll
            for (int i = 0; i < 4; i++) {
                CP16(st + OFF_AH + so[i], Ahi + a_base + kc + i * 8);
                CP16(st + OFF_AL + so[i], Alo + a_base + kc + i * 8);
                CP16(st + OFF_BH + so[i], Bhi + b_base + kc + i * 8);
                CP16(st + OFF_BL + so[i], Blo + b_base + kc + i * 8);
            }
            CP_COMMIT();
            CP_WAIT1();
        } else {
            CP_WAIT0();
        }
        __syncthreads();

        const uint32_t sb = tb + (c & 1) * STAGE_BYTES;
#pragma unroll
        for (int ks = 0; ks < 4; ks++) {
            uint32_t ah[4][4], al[4][4], bh[2][4], bl[2][4];
            const uint32_t cba = (uint32_t)(ks * 32 + ka);
#pragma unroll
            for (int mt = 0; mt < 4; mt++) {
                const uint32_t off = aoff[mt] + (cba ^ xA[mt]);
                LDSM4(ah[mt], sb + OFF_AH + off);
                LDSM4(al[mt], sb + OFF_AL + off);
            }
            const uint32_t cbb = (uint32_t)(ks * 32 + kb);
#pragma unroll
            for (int p = 0; p < 2; p++) {
                const uint32_t off = boff[p] + (cbb ^ xB[p]);
                LDSM4(bh[p], sb + OFF_BH + off);
                LDSM4(bl[p], sb + OFF_BL + off);
            }
            // term-outer: same-acc MMAs are 16 issues apart
#pragma unroll
            for (int mt = 0; mt < 4; mt++)
#pragma unroll
                for (int nt = 0; nt < 4; nt++) {
                    const int p = nt >> 1, q = (nt & 1) * 2;
                    MMA16816(acc[mt][nt], ah[mt], bh[p][q], bh[p][q + 1]);
                }
#pragma unroll
            for (int mt = 0; mt < 4; mt++)
#pragma unroll
                for (int nt = 0; nt < 4; nt++) {
                    const int p = nt >> 1, q = (nt & 1) * 2;
                    MMA16816(acc[mt][nt], ah[mt], bl[p][q], bl[p][q + 1]);
                }
#pragma unroll
            for (int mt = 0; mt < 4; mt++)
#pragma unroll
                for (int nt = 0; nt < 4; nt++) {
                    const int p = nt >> 1, q = (nt & 1) * 2;
                    MMA16816(acc[mt][nt], al[mt], bh[p][q], bh[p][q + 1]);
                }
        }
        __syncthreads();
    }

    const int mrow = lane >> 2;
    const int ncol = (lane & 3) * 2;
#pragma unroll
    for (int mt = 0; mt < 4; mt++) {
#pragma unroll
        for (int half = 0; half < 2; half++) {
            const int r = row0 + wr * 64 + mt * 16 + mrow + half * 8;
#pragma unroll
            for (int nt = 0; nt < 4; nt++) {
                float v0 = acc[mt][nt][half * 2 + 0];
                float v1 = acc[mt][nt][half * 2 + 1];
                const int cc = col0 + wc * 32 + nt * 8 + ncol;
                if (bias) { v0 += bias[cc]; v1 += bias[cc + 1]; }
                if (do_gelu) { v0 = gelu_f(v0); v1 = gelu_f(v1); }
                if (res) {
                    v0 += res[(size_t)r * N + cc];
                    v1 += res[(size_t)r * N + cc + 1];
                }
                if (C) *(float2*)(C + (size_t)r * N + cc) = make_float2(v0, v1);
                if (Chi) {
                    unsigned short h0, l0, h1, l1;
                    bsplit(v0, h0, l0);
                    bsplit(v1, h1, l1);
                    *(uint32_t*)(Chi + (size_t)r * N + cc) = (uint32_t)h0 | ((uint32_t)h1 << 16);
                    *(uint32_t*)(Clo + (size_t)r * N + cc) = (uint32_t)l0 | ((uint32_t)l1 << 16);
                }
            }
        }
    }
}

// ---------------------------------------------------------------------------
// Fused flash attention with stride-parametrized Q / KV (packed layouts).
// ---------------------------------------------------------------------------
constexpr int FQ_H = 0;
constexpr int FQ_L = 16384;
constexpr int FKV0 = 32768;
constexpr int FK_H = 0, FK_L = 16384, FV_H = 32768, FV_L = 49152;
constexpr int FSTG = 65536;
constexpr int FLASH_SMEM = 32768 + 2 * FSTG + 1024;

__global__ void __launch_bounds__(256, 1)
flash_attn(const uint16_t* __restrict__ Qhi, const uint16_t* __restrict__ Qlo,
           const uint16_t* __restrict__ Khi, const uint16_t* __restrict__ Klo,
           const uint16_t* __restrict__ Vhi, const uint16_t* __restrict__ Vlo,
           uint16_t* __restrict__ Ohi, uint16_t* __restrict__ Olo,
           int Tq, int Tk, int strQ, int strKV, int causal) {
    extern __shared__ uint8_t dsm[];
    uint8_t* basep = (uint8_t*)(((uintptr_t)dsm + 1023) & ~(uintptr_t)1023);
    const uint32_t tb = smem_u32(basep);

    const int bh = blockIdx.y;
    const int b = bh >> 4, h = bh & 15;
    int it = blockIdx.x;
    if (causal) it = (int)gridDim.x - 1 - it;
    const int i0 = it * 128;
    const int NJ = causal ? (it + 1) : (Tk >> 7);

    const int tid = threadIdx.x;
    const int lane = tid & 31;
    const int wid = tid >> 5;

    const int lrow = tid >> 1, lhalf = tid & 1;
    uint32_t so[4];
#pragma unroll
    for (int i = 0; i < 4; i++) {
        uint32_t o = (uint32_t)lrow * 128 + (uint32_t)lhalf * 64 + i * 16;
        so[i] = o ^ ((o >> 3) & 0x70);
    }
    const size_t qg = (size_t)(b * Tq + i0 + lrow) * strQ + h * cfg::HD + lhalf * 32;
    const size_t kg = (size_t)(b * Tk + lrow) * strKV + h * cfg::HD + lhalf * 32;

#pragma unroll
    for (int i = 0; i < 4; i++) {
        CP16(tb + FQ_H + so[i], Qhi + qg + i * 8);
        CP16(tb + FQ_L + so[i], Qlo + qg + i * 8);
    }
    {
        const uint32_t st = tb + FKV0;
#pragma unroll
        for (int i = 0; i < 4; i++) {
            CP16(st + FK_H + so[i], Khi + kg + i * 8);
            CP16(st + FK_L + so[i], Klo + kg + i * 8);
            CP16(st + FV_H + so[i], Vhi + kg + i * 8);
            CP16(st + FV_L + so[i], Vlo + kg + i * 8);
        }
    }
    CP_COMMIT();

    const int arow = wid * 16 + (lane & 15);
    const uint32_t aoff = (uint32_t)arow * 128;
    const uint32_t axr  = (uint32_t)(arow & 7) * 16;
    const int ka = (lane >> 4) * 16;
    const int nrow_b = ((lane >> 4) & 1) * 8 + (lane & 7);
    const int kb = ((lane >> 3) & 1) * 16;
    const int vm = lane >> 3;
    const int vrow_b = (vm & 1) * 8 + (lane & 7);
    const int vcol_b = (vm >> 1) * 16;

    uint32_t qh[4][4], ql[4][4];
    float accO[8][4];
#pragma unroll
    for (int nt = 0; nt < 8; nt++)
#pragma unroll
        for (int e = 0; e < 4; e++) accO[nt][e] = 0.0f;
    float m2[2] = {-3.0e38f, -3.0e38f};
    float lsum[2] = {0.0f, 0.0f};

    const int mrow = lane >> 2;
    const int cb = (lane & 3) * 2;
    const int irow0 = i0 + wid * 16 + mrow;
    const int irow1 = irow0 + 8;

    for (int jt = 0; jt < NJ; jt++) {
        if (jt + 1 < NJ) {
            const uint32_t st = tb + FKV0 + ((jt + 1) & 1) * FSTG;
            const size_t kgj = kg + (size_t)(jt + 1) * 128 * strKV;
#pragma unroll
            for (int i = 0; i < 4; i++) {
                CP16(st + FK_H + so[i], Khi + kgj + i * 8);
                CP16(st + FK_L + so[i], Klo + kgj + i * 8);
                CP16(st + FV_H + so[i], Vhi + kgj + i * 8);
                CP16(st + FV_L + so[i], Vlo + kgj + i * 8);
            }
            CP_COMMIT();
            CP_WAIT1();
        } else {
            CP_WAIT0();
        }
        __syncthreads();

        if (jt == 0) {
#pragma unroll
            for (int ks = 0; ks < 4; ks++) {
                const uint32_t off = aoff + (((uint32_t)(ks * 32 + ka)) ^ axr);
                LDSM4(qh[ks], tb + FQ_H + off);
                LDSM4(ql[ks], tb + FQ_L + off);
            }
        }
        const uint32_t sb = tb + FKV0 + (jt & 1) * FSTG;

        float accS[16][4];
#pragma unroll
        for (int nt = 0; nt < 16; nt++)
#pragma unroll
            for (int e = 0; e < 4; e++) accS[nt][e] = 0.0f;

#pragma unroll
        for (int ks = 0; ks < 4; ks++) {
            const uint32_t cbb = (uint32_t)(ks * 32 + kb);
#pragma unroll
            for (int ntp = 0; ntp < 8; ntp++) {
                const int r = ntp * 16 + nrow_b;
                const uint32_t off = (uint32_t)r * 128 + (cbb ^ ((uint32_t)(r & 7) * 16));
                uint32_t bh4[4], bl4[4];
                LDSM4(bh4, sb + FK_H + off);
                LDSM4(bl4, sb + FK_L + off);
                // interleaved terms: same-acc MMAs 2 apart, ptxas free to stretch
                MMA16816(accS[2 * ntp],     qh[ks], bh4[0], bh4[1]);
                MMA16816(accS[2 * ntp + 1], qh[ks], bh4[2], bh4[3]);
                MMA16816(accS[2 * ntp],     qh[ks], bl4[0], bl4[1]);
                MMA16816(accS[2 * ntp + 1], qh[ks], bl4[2], bl4[3]);
                MMA16816(accS[2 * ntp],     ql[ks], bh4[0], bh4[1]);
                MMA16816(accS[2 * ntp + 1], ql[ks], bh4[2], bh4[3]);
            }
        }

        const int j0 = jt * 128;
        const bool maskTile = causal && (jt == NJ - 1);
#pragma unroll
        for (int nt = 0; nt < 16; nt++)
#pragma unroll
            for (int e = 0; e < 4; e++) accS[nt][e] *= cfg::SC2;
        if (maskTile) {
#pragma unroll
            for (int nt = 0; nt < 16; nt++) {
                const int jc = j0 + nt * 8 + cb;
                if (jc     > irow0) accS[nt][0] = -3.0e38f;
                if (jc + 1 > irow0) accS[nt][1] = -3.0e38f;
                if (jc     > irow1) accS[nt][2] = -3.0e38f;
                if (jc + 1 > irow1) accS[nt][3] = -3.0e38f;
            }
        }

        float mx0 = -3.0e38f, mx1 = -3.0e38f;
#pragma unroll
        for (int nt = 0; nt < 16; nt++) {
            mx0 = fmaxf(mx0, fmaxf(accS[nt][0], accS[nt][1]));
            mx1 = fmaxf(mx1, fmaxf(accS[nt][2], accS[nt][3]));
        }
        mx0 = fmaxf(mx0, __shfl_xor_sync(0xffffffffu, mx0, 1));
        mx0 = fmaxf(mx0, __shfl_xor_sync(0xffffffffu, mx0, 2));
        mx1 = fmaxf(mx1, __shfl_xor_sync(0xffffffffu, mx1, 1));
        mx1 = fmaxf(mx1, __shfl_xor_sync(0xffffffffu, mx1, 2));
        const float mn0 = fmaxf(m2[0], mx0);
        const float mn1 = fmaxf(m2[1], mx1);
        const float al0 = exp2f(m2[0] - mn0);
        const float al1 = exp2f(m2[1] - mn1);
        m2[0] = mn0; m2[1] = mn1;

        float s0 = 0.0f, s1 = 0.0f;
#pragma unroll
        for (int nt = 0; nt < 16; nt++) {
            float p0 = exp2f(accS[nt][0] - mn0);
            float p1 = exp2f(accS[nt][1] - mn0);
            float p2 = exp2f(accS[nt][2] - mn1);
            float p3 = exp2f(accS[nt][3] - mn1);
            accS[nt][0] = p0; accS[nt][1] = p1;
            accS[nt][2] = p2; accS[nt][3] = p3;
            s0 += p0 + p1;
            s1 += p2 + p3;
        }
        s0 += __shfl_xor_sync(0xffffffffu, s0, 1);
        s0 += __shfl_xor_sync(0xffffffffu, s0, 2);
        s1 += __shfl_xor_sync(0xffffffffu, s1, 1);
        s1 += __shfl_xor_sync(0xffffffffu, s1, 2);
        lsum[0] = lsum[0] * al0 + s0;
        lsum[1] = lsum[1] * al1 + s1;

#pragma unroll
        for (int nt = 0; nt < 8; nt++) {
            accO[nt][0] *= al0; accO[nt][1] *= al0;
            accO[nt][2] *= al1; accO[nt][3] *= al1;
        }

#pragma unroll
        for (int ks = 0; ks < 8; ks++) {
            uint32_t ph[4], pl[4];
#pragma unroll
            for (int q = 0; q < 2; q++) {
                const float p0 = accS[2 * ks + q][0];
                const float p1 = accS[2 * ks + q][1];
                const float p2 = accS[2 * ks + q][2];
                const float p3 = accS[2 * ks + q][3];
                uint32_t h01, h23;
                CVTPK(h01, p1, p0);
                CVTPK(h23, p3, p2);
                ph[2 * q]     = h01;
                ph[2 * q + 1] = h23;
                const float l0 = p0 - __uint_as_float(h01 << 16);
                const float l1 = p1 - __uint_as_float(h01 & 0xFFFF0000u);
                const float l2 = p2 - __uint_as_float(h23 << 16);
                const float l3 = p3 - __uint_as_float(h23 & 0xFFFF0000u);
                uint32_t u01, u23;
                CVTPK(u01, l1, l0);
                CVTPK(u23, l3, l2);
                pl[2 * q]     = u01;
                pl[2 * q + 1] = u23;
            }
            const int jr = ks * 16 + vrow_b;
            const uint32_t roff = (uint32_t)jr * 128;
            const uint32_t xr = (uint32_t)(jr & 7) * 16;
#pragma unroll
            for (int ntp = 0; ntp < 4; ntp++) {
                const uint32_t off = roff + (((uint32_t)(ntp * 32 + vcol_b)) ^ xr);
                uint32_t vh4[4], vl4[4];
                LDSM4T(vh4, sb + FV_H + off);
                LDSM4T(vl4, sb + FV_L + off);
                MMA16816(accO[2 * ntp],     ph, vh4[0], vh4[1]);
                MMA16816(accO[2 * ntp + 1], ph, vh4[2], vh4[3]);
                MMA16816(accO[2 * ntp],     ph, vl4[0], vl4[1]);
                MMA16816(accO[2 * ntp + 1], ph, vl4[2], vl4[3]);
                MMA16816(accO[2 * ntp],     pl, vh4[0], vh4[1]);
                MMA16816(accO[2 * ntp + 1], pl, vh4[2], vh4[3]);
            }
        }
        __syncthreads();
    }

    const float li0 = 1.0f / lsum[0];
    const float li1 = 1.0f / lsum[1];
#pragma unroll
    for (int nt = 0; nt < 8; nt++) {
        const float v0 = accO[nt][0] * li0;
        const float v1 = accO[nt][1] * li0;
        const float v2 = accO[nt][2] * li1;
        const float v3 = accO[nt][3] * li1;
        unsigned short h0, l0, h1, l1, h2, l2, h3, l3;
        bsplit(v0, h0, l0); bsplit(v1, h1, l1);
        bsplit(v2, h2, l2); bsplit(v3, h3, l3);
        const int d = h * cfg::HD + nt * 8 + cb;
        const size_t o0 = (size_t)(b * Tq + irow0) * cfg::E + d;
        const size_t o1 = (size_t)(b * Tq + irow1) * cfg::E + d;
        *(uint32_t*)(Ohi + o0) = (uint32_t)h0 | ((uint32_t)h1 << 16);
        *(uint32_t*)(Olo + o0) = (uint32_t)l0 | ((uint32_t)l1 << 16);
        *(uint32_t*)(Ohi + o1) = (uint32_t)h2 | ((uint32_t)h3 << 16);
        *(uint32_t*)(Olo + o1) = (uint32_t)l2 | ((uint32_t)l3 << 16);
    }
}

// ---------------------------------------------------------------------------
// LayerNorm emitting bf16 hi/lo
// ---------------------------------------------------------------------------
__global__ void ln_split(const float* __restrict__ X, const float* __restrict__ gam,
                         const float* __restrict__ bet, uint16_t* __restrict__ Hi,
                         uint16_t* __restrict__ Lo) {
    __shared__ float red[256];
    const int row = blockIdx.x;
    const int tid = threadIdx.x;
    const float4 v = ((const float4*)(X + (size_t)row * cfg::E))[tid];

    float s = v.x + v.y + v.z + v.w;
    red[tid] = s; __syncthreads();
    for (int off = 128; off; off >>= 1) {
        if (tid < off) red[tid] += red[tid + off];
        __syncthreads();
    }
    const float mu = red[0] * (1.0f / cfg::E);
    __syncthreads();

    const float dx = v.x - mu, dy = v.y - mu, dz = v.z - mu, dw = v.w - mu;
    red[tid] = dx*dx + dy*dy + dz*dz + dw*dw; __syncthreads();
    for (int off = 128; off; off >>= 1) {
        if (tid < off) red[tid] += red[tid + off];
        __syncthreads();
    }
    const float var = red[0] * (1.0f / cfg::E);
    const float r = rsqrtf(var + 1e-5f);

    const float4 g4 = ((const float4*)gam)[tid];
    const float4 b4 = ((const float4*)bet)[tid];
    float o[4];
    o[0] = dx * r * g4.x + b4.x;
    o[1] = dy * r * g4.y + b4.y;
    o[2] = dz * r * g4.z + b4.z;
    o[3] = dw * r * g4.w + b4.w;
    ushort4 ho, lo;
    unsigned short hs[4], ls[4];
#pragma unroll
    for (int c = 0; c < 4; c++) bsplit(o[c], hs[c], ls[c]);
    ho.x = hs[0]; ho.y = hs[1]; ho.z = hs[2]; ho.w = hs[3];
    lo.x = ls[0]; lo.y = ls[1]; lo.z = ls[2]; lo.w = ls[3];
    ((ushort4*)(Hi + (size_t)row * cfg::E))[tid] = ho;
    ((ushort4*)(Lo + (size_t)row * cfg::E))[tid] = lo;
}

__global__ void split_f32(const float* __restrict__ X, uint16_t* __restrict__ Hi,
                          uint16_t* __restrict__ Lo, int n4) {
    const int i = blockIdx.x * 256 + threadIdx.x;
    if (i >= n4) return;
    const float4 v = ((const float4*)X)[i];
    float xs[4] = {v.x, v.y, v.z, v.w};
    unsigned short hs[4], ls[4];
#pragma unroll
    for (int c = 0; c < 4; c++) bsplit(xs[c], hs[c], ls[c]);
    ushort4 ho, lo;
    ho.x = hs[0]; ho.y = hs[1]; ho.z = hs[2]; ho.w = hs[3];
    lo.x = ls[0]; lo.y = ls[1]; lo.z = ls[2]; lo.w = ls[3];
    ((ushort4*)Hi)[i] = ho;
    ((ushort4*)Lo)[i] = lo;
}

__global__ void transpose_split(const float* __restrict__ W, uint16_t* __restrict__ Hi,
                                uint16_t* __restrict__ Lo, int Kd, int Nd) {
    __shared__ float tile[32][33];
    const int n0 = blockIdx.x * 32, k0 = blockIdx.y * 32;
    const int tx = threadIdx.x, ty = threadIdx.y;
    for (int r = ty; r < 32; r += 8)
        tile[r][tx] = W[(size_t)(k0 + r) * Nd + n0 + tx];
    __syncthreads();
    for (int r = ty; r < 32; r += 8) {
        const float x = tile[tx][r];
        unsigned short h, l;
        bsplit(x, h, l);
        const size_t o = (size_t)(n0 + r) * Kd + k0 + tx;
        Hi[o] = h;
        Lo[o] = l;
    }
}

// ---------------------------------------------------------------------------
// Launch sequence
// ---------------------------------------------------------------------------
extern "C" void kernel_launch(void* const* d_in, const int* in_sizes, int n_in,
                              void* d_out, int out_size) {
    using namespace cfg;
    const float* x        = (const float*)d_in[0];
    const float* context  = (const float*)d_in[1];
    const float* ln1_g    = (const float*)d_in[2];
    const float* ln1_b    = (const float*)d_in[3];
    const float* ln2_g    = (const float*)d_in[4];
    const float* ln2_b    = (const float*)d_in[5];
    const float* ln3_g    = (const float*)d_in[6];
    const float* ln3_b    = (const float*)d_in[7];
    const float* Wq_s     = (const float*)d_in[8];
    const float* Wk_s     = (const float*)d_in[9];
    const float* Wv_s     = (const float*)d_in[10];
    const float* proj_s_w = (const float*)d_in[11];
    const float* proj_s_b = (const float*)d_in[12];
    const float* Wq_c     = (const float*)d_in[13];
    const float* Wk_c     = (const float*)d_in[14];
    const float* Wv_c     = (const float*)d_in[15];
    const float* proj_c_w = (const float*)d_in[16];
    const float* proj_c_b = (const float*)d_in[17];
    const float* w1       = (const float*)d_in[18];
    const float* b1       = (const float*)d_in[19];
    const float* w2       = (const float*)d_in[20];
    const float* b2       = (const float*)d_in[21];
    float* out = (float*)d_out;

    float *px1, *px2;
    uint16_t *ahi, *alo, *bhi, *blo, *qhi, *qlo, *fhi, *flo;
    cudaGetSymbolAddress((void**)&px1, g_x1);
    cudaGetSymbolAddress((void**)&px2, g_x2);
    cudaGetSymbolAddress((void**)&ahi, g_ahi);
    cudaGetSymbolAddress((void**)&alo, g_alo);
    cudaGetSymbolAddress((void**)&bhi, g_bhi);
    cudaGetSymbolAddress((void**)&blo, g_blo);
    cudaGetSymbolAddress((void**)&qhi, g_qhi);
    cudaGetSymbolAddress((void**)&qlo, g_qlo);
    cudaGetSymbolAddress((void**)&fhi, g_fhi);
    cudaGetSymbolAddress((void**)&flo, g_flo);
    uint16_t* chi = ahi + (size_t)8 * 1024 * 1024;
    uint16_t* clo = alo + (size_t)8 * 1024 * 1024;

    const int GEMM_SMEM = 2 * STAGE_BYTES + 1024;
    cudaFuncSetAttribute(tc_gemm, cudaFuncAttributeMaxDynamicSharedMemorySize, GEMM_SMEM);
    cudaFuncSetAttribute(flash_attn, cudaFuncAttributeMaxDynamicSharedMemorySize, FLASH_SMEM);

    const int M = B * T;
    const dim3 gE   (E / 128,       M / 128);   // (8, 32)
    const dim3 gQKV (3 * E / 128,   M / 128);   // (24, 32)
    const dim3 gKV  (2 * E / 128,   M / 128);   // (16, 32)
    const dim3 g4E  (4 * E / 128,   M / 128);   // (32, 32)
    const dim3 gfl  (T / 128, BH);
    const int nME4 = (M * E) / 4;
    const dim3 gtEE (E / 32, E / 32);
    const dim3 gtE4 (4 * E / 32, E / 32);
    const dim3 gt4E (E / 32, 4 * E / 32);
    const dim3 tbt(32, 8);

    // ---- self attention (causal): merged QKV ----
    ln_split<<<M, 256>>>(x, ln1_g, ln1_b, ahi, alo);
    transpose_split<<<gtEE, tbt>>>(Wq_s, bhi,                   blo,                   E, E);
    transpose_split<<<gtEE, tbt>>>(Wk_s, bhi + (size_t)E * E,   blo + (size_t)E * E,   E, E);
    transpose_split<<<gtEE, tbt>>>(Wv_s, bhi + (size_t)2*E*E,   blo + (size_t)2*E*E,   E, E);
    tc_gemm<<<gQKV, 256, GEMM_SMEM>>>(ahi, alo, bhi, blo, nullptr, nullptr,
                                      nullptr, fhi, flo, 3 * E, E, 0);
    flash_attn<<<gfl, 256, FLASH_SMEM>>>(fhi, flo, fhi + E, flo + E, fhi + 2 * E, flo + 2 * E,
                                         ahi, alo, T, S, 3 * E, 3 * E, 1);
    transpose_split<<<gtEE, tbt>>>(proj_s_w, bhi, blo, E, E);
    tc_gemm<<<gE, 256, GEMM_SMEM>>>(ahi, alo, bhi, blo, proj_s_b, x,
                                    px1, nullptr, nullptr, E, E, 0);

    // ---- cross attention: q separate, merged KV from context ----
    ln_split<<<M, 256>>>(px1, ln2_g, ln2_b, ahi, alo);
    transpose_split<<<gtEE, tbt>>>(Wq_c, bhi, blo, E, E);
    tc_gemm<<<gE, 256, GEMM_SMEM>>>(ahi, alo, bhi, blo, nullptr, nullptr,
                                    nullptr, qhi, qlo, E, E, 0);
    split_f32<<<(nME4 + 255) / 256, 256>>>(context, chi, clo, nME4);
    transpose_split<<<gtEE, tbt>>>(Wk_c, bhi,                 blo,                 E, E);
    transpose_split<<<gtEE, tbt>>>(Wv_c, bhi + (size_t)E * E, blo + (size_t)E * E, E, E);
    tc_gemm<<<gKV, 256, GEMM_SMEM>>>(chi, clo, bhi, blo, nullptr, nullptr,
                                     nullptr, fhi, flo, 2 * E, E, 0);
    flash_attn<<<gfl, 256, FLASH_SMEM>>>(qhi, qlo, fhi, flo, fhi + E, flo + E,
                                         ahi, alo, T, S, E, 2 * E, 0);
    transpose_split<<<gtEE, tbt>>>(proj_c_w, bhi, blo, E, E);
    tc_gemm<<<gE, 256, GEMM_SMEM>>>(ahi, alo, bhi, blo, proj_c_b, px1,
                                    px2, nullptr, nullptr, E, E, 0);

    // ---- FFN ----
    ln_split<<<M, 256>>>(px2, ln3_g, ln3_b, ahi, alo);
    transpose_split<<<gtE4, tbt>>>(w1, bhi, blo, E, 4 * E);
    tc_gemm<<<g4E, 256, GEMM_SMEM>>>(ahi, alo, bhi, blo, b1, nullptr,
                                     nullptr, fhi, flo, 4 * E, E, 1);
    transpose_split<<<gt4E, tbt>>>(w2, bhi, blo, 4 * E, E);
    tc_gemm<<<gE, 256, GEMM_SMEM>>>(fhi, flo, bhi, blo, b2, px2,
                                    out, nullptr, nullptr, E, 4 * E, 0);
}

// round 8
// speedup vs baseline: 6.3273x; 2.3318x over previous
#include <cuda_runtime.h>
#include <cuda_bf16.h>
#include <cuda_fp16.h>
#include <math.h>
#include <stdint.h>

// ---------------------------------------------------------------------------
// DecoderLayerWithContext — Round 8 (Round-7 resubmit; infra failed twice)
// ALL GEMMs + flash attention in plain fp16 (fp32 accumulate).
// Rationale: R6 null => mma.sync path is issue/byte-throughput bound;
// fp16 single-pass cuts MMA count 3x and operand bytes 2x vs bf16x3.
// Residuals/bias/softmax/LN all fp32. Predicted rel_err ~4e-4 (<1e-3).
// ---------------------------------------------------------------------------

namespace cfg {
constexpr int E  = 1024;
constexpr int NH = 16;
constexpr int HD = 64;
constexpr int B  = 2;
constexpr int T  = 2048;
constexpr int S  = 2048;
constexpr int BH = B * NH;
constexpr float SC2 = 0.03125f * 1.44269504f;   // (1/sqrt(E)) * log2(e)
}

// -------------------------- device scratch ---------------------------------
__device__ float    g_x1[cfg::B * cfg::T * cfg::E];
__device__ float    g_x2[cfg::B * cfg::T * cfg::E];
__device__ uint16_t g_a [(size_t)4  * 1024 * 1024];   // activations (fp16 bits)
__device__ uint16_t g_c [(size_t)4  * 1024 * 1024];   // context fp16
__device__ uint16_t g_b [(size_t)4  * 1024 * 1024];   // transposed weights fp16
__device__ uint16_t g_q [(size_t)4  * 1024 * 1024];   // q / ln3 / flash-out swap
__device__ uint16_t g_f [(size_t)16 * 1024 * 1024];   // wide intermediate fp16

// -------------------------- asm helpers ------------------------------------
__device__ __forceinline__ uint32_t smem_u32(const void* p) {
    uint32_t a;
    asm("{ .reg .u64 t; cvta.to.shared.u64 t, %1; cvt.u32.u64 %0, t; }" : "=r"(a) : "l"(p));
    return a;
}
#define CP16(s, g) \
    asm volatile("cp.async.cg.shared.global [%0], [%1], 16;" :: "r"(s), "l"(g))
#define CP_COMMIT()  asm volatile("cp.async.commit_group;" ::: "memory")
#define CP_WAIT0()   asm volatile("cp.async.wait_group 0;" ::: "memory")
#define CP_WAIT1()   asm volatile("cp.async.wait_group 1;" ::: "memory")

#define LDSM4(r, addr)                                                        \
    asm volatile("ldmatrix.sync.aligned.m8n8.x4.shared.b16 {%0,%1,%2,%3}, [%4];" \
        : "=r"((r)[0]), "=r"((r)[1]), "=r"((r)[2]), "=r"((r)[3]) : "r"(addr))
#define LDSM4T(r, addr)                                                       \
    asm volatile("ldmatrix.sync.aligned.m8n8.x4.trans.shared.b16 {%0,%1,%2,%3}, [%4];" \
        : "=r"((r)[0]), "=r"((r)[1]), "=r"((r)[2]), "=r"((r)[3]) : "r"(addr))

#define MMAH(d, a, b0, b1)                                                    \
    asm("mma.sync.aligned.m16n8k16.row.col.f32.f16.f16.f32 "                  \
        "{%0,%1,%2,%3},{%4,%5,%6,%7},{%8,%9},{%0,%1,%2,%3};"                  \
        : "+f"((d)[0]), "+f"((d)[1]), "+f"((d)[2]), "+f"((d)[3])              \
        : "r"((a)[0]), "r"((a)[1]), "r"((a)[2]), "r"((a)[3]), "r"(b0), "r"(b1))

__device__ __forceinline__ uint32_t packh2(float lo, float hi) {
    __half2 h = __floats2half2_rn(lo, hi);
    return *reinterpret_cast<uint32_t*>(&h);
}
__device__ __forceinline__ unsigned short h16(float x) {
    __half h = __float2half_rn(x);
    return *reinterpret_cast<unsigned short*>(&h);
}
__device__ __forceinline__ float gelu_f(float x) {
    return 0.5f * x * (1.0f + erff(x * 0.7071067811865475f));
}

// ---------------------------------------------------------------------------
// fp16 HMMA GEMM: C[M,N] = epi(A[M,K] * B[N,K]^T)
// Tile 128x128, K chunks of 64, 8 warps (2x4) of 64x32 microtiles,
// double-buffered cp.async. Stage = A(16KB)+B(16KB) -> 2 CTAs/SM.
// ---------------------------------------------------------------------------
constexpr int H_OFF_B = 16384;
constexpr int H_STAGE = 32768;

__global__ void __launch_bounds__(256, 2)
hgemm(const uint16_t* __restrict__ A, const uint16_t* __restrict__ Bm,
      const float* __restrict__ bias, const float* __restrict__ res,
      float* __restrict__ C, uint16_t* __restrict__ Ch,
      int N, int K, int do_gelu) {
    extern __shared__ uint8_t dsm[];
    uint8_t* tiles = (uint8_t*)(((uintptr_t)dsm + 1023) & ~(uintptr_t)1023);
    const uint32_t tb = smem_u32(tiles);

    const int tid  = threadIdx.x;
    const int lane = tid & 31;
    const int wid  = tid >> 5;
    const int wr   = wid >> 2;
    const int wc   = wid & 3;
    const int row0 = blockIdx.y * 128;
    const int col0 = blockIdx.x * 128;

    const int lrow = tid >> 1, lhalf = tid & 1;
    uint32_t so[4];
#pragma unroll
    for (int i = 0; i < 4; i++) {
        uint32_t o = (uint32_t)lrow * 128 + (uint32_t)lhalf * 64 + i * 16;
        so[i] = o ^ ((o >> 3) & 0x70);
    }
    const size_t a_base = (size_t)(row0 + lrow) * K + lhalf * 32;
    const size_t b_base = (size_t)(col0 + lrow) * K + lhalf * 32;

    const int ka = (lane >> 4) * 16;
    const int kb = ((lane >> 3) & 1) * 16;
    uint32_t aoff[4], xA[4];
#pragma unroll
    for (int mt = 0; mt < 4; mt++) {
        int r = wr * 64 + mt * 16 + (lane & 15);
        aoff[mt] = (uint32_t)r * 128;
        xA[mt] = (uint32_t)(r & 7) * 16;
    }
    uint32_t boff[2], xB[2];
#pragma unroll
    for (int p = 0; p < 2; p++) {
        int r = wc * 32 + p * 16 + ((lane >> 4) & 1) * 8 + (lane & 7);
        boff[p] = (uint32_t)r * 128;
        xB[p] = (uint32_t)(r & 7) * 16;
    }

    float acc[4][4][4];
#pragma unroll
    for (int mt = 0; mt < 4; mt++)
#pragma unroll
        for (int nt = 0; nt < 4; nt++)
#pragma unroll
            for (int e = 0; e < 4; e++) acc[mt][nt][e] = 0.0f;

    const int NC = K >> 6;
    {
#pragma unroll
        for (int i = 0; i < 4; i++) {
            CP16(tb + so[i],           A  + a_base + i * 8);
            CP16(tb + H_OFF_B + so[i], Bm + b_base + i * 8);
        }
        CP_COMMIT();
    }

    for (int c = 0; c < NC; c++) {
        if (c + 1 < NC) {
            const uint32_t st = tb + ((c + 1) & 1) * H_STAGE;
            const int kc = (c + 1) << 6;
#pragma unroll
            for (int i = 0; i < 4; i++) {
                CP16(st + so[i],           A  + a_base + kc + i * 8);
                CP16(st + H_OFF_B + so[i], Bm + b_base + kc + i * 8);
            }
            CP_COMMIT();
            CP_WAIT1();
        } else {
            CP_WAIT0();
        }
        __syncthreads();

        const uint32_t sb = tb + (c & 1) * H_STAGE;
#pragma unroll
        for (int ks = 0; ks < 4; ks++) {
            uint32_t ah[4][4], bh[2][4];
            const uint32_t cba = (uint32_t)(ks * 32 + ka);
#pragma unroll
            for (int mt = 0; mt < 4; mt++)
                LDSM4(ah[mt], sb + aoff[mt] + (cba ^ xA[mt]));
            const uint32_t cbb = (uint32_t)(ks * 32 + kb);
#pragma unroll
            for (int p = 0; p < 2; p++)
                LDSM4(bh[p], sb + H_OFF_B + boff[p] + (cbb ^ xB[p]));
#pragma unroll
            for (int mt = 0; mt < 4; mt++)
#pragma unroll
                for (int nt = 0; nt < 4; nt++) {
                    const int p = nt >> 1, q = (nt & 1) * 2;
                    MMAH(acc[mt][nt], ah[mt], bh[p][q], bh[p][q + 1]);
                }
        }
        __syncthreads();
    }

    const int mrow = lane >> 2;
    const int ncol = (lane & 3) * 2;
#pragma unroll
    for (int mt = 0; mt < 4; mt++) {
#pragma unroll
        for (int half = 0; half < 2; half++) {
            const int r = row0 + wr * 64 + mt * 16 + mrow + half * 8;
#pragma unroll
            for (int nt = 0; nt < 4; nt++) {
                float v0 = acc[mt][nt][half * 2 + 0];
                float v1 = acc[mt][nt][half * 2 + 1];
                const int cc = col0 + wc * 32 + nt * 8 + ncol;
                if (bias) { v0 += bias[cc]; v1 += bias[cc + 1]; }
                if (do_gelu) { v0 = gelu_f(v0); v1 = gelu_f(v1); }
                if (res) {
                    v0 += res[(size_t)r * N + cc];
                    v1 += res[(size_t)r * N + cc + 1];
                }
                if (C) *(float2*)(C + (size_t)r * N + cc) = make_float2(v0, v1);
                if (Ch) *(uint32_t*)(Ch + (size_t)r * N + cc) = packh2(v0, v1);
            }
        }
    }
}

// ---------------------------------------------------------------------------
// Fused flash attention, fp16 Q/K/V. Output fp16 [.., E].
// 128 q-rows/CTA, 8 warps x 16 rows. smem: Q 16KB + 2 x (K16+V16)KB.
// ---------------------------------------------------------------------------
constexpr int F_KV0 = 16384;
constexpr int F_V   = 16384;
constexpr int F_STG = 32768;
constexpr int FLASH_SMEM = 16384 + 2 * F_STG + 1024;

__global__ void __launch_bounds__(256, 1)
flash_h(const uint16_t* __restrict__ Q, const uint16_t* __restrict__ Kp,
        const uint16_t* __restrict__ Vp, uint16_t* __restrict__ Oh,
        int Tq, int Tk, int strQ, int strKV, int causal) {
    extern __shared__ uint8_t dsm[];
    uint8_t* basep = (uint8_t*)(((uintptr_t)dsm + 1023) & ~(uintptr_t)1023);
    const uint32_t tb = smem_u32(basep);

    const int bh = blockIdx.y;
    const int b = bh >> 4, h = bh & 15;
    int it = blockIdx.x;
    if (causal) it = (int)gridDim.x - 1 - it;
    const int i0 = it * 128;
    const int NJ = causal ? (it + 1) : (Tk >> 7);

    const int tid = threadIdx.x;
    const int lane = tid & 31;
    const int wid = tid >> 5;

    const int lrow = tid >> 1, lhalf = tid & 1;
    uint32_t so[4];
#pragma unroll
    for (int i = 0; i < 4; i++) {
        uint32_t o = (uint32_t)lrow * 128 + (uint32_t)lhalf * 64 + i * 16;
        so[i] = o ^ ((o >> 3) & 0x70);
    }
    const size_t qg = (size_t)(b * Tq + i0 + lrow) * strQ + h * cfg::HD + lhalf * 32;
    const size_t kg = (size_t)(b * Tk + lrow) * strKV + h * cfg::HD + lhalf * 32;

#pragma unroll
    for (int i = 0; i < 4; i++) CP16(tb + so[i], Q + qg + i * 8);
    {
        const uint32_t st = tb + F_KV0;
#pragma unroll
        for (int i = 0; i < 4; i++) {
            CP16(st + so[i],       Kp + kg + i * 8);
            CP16(st + F_V + so[i], Vp + kg + i * 8);
        }
    }
    CP_COMMIT();

    const int arow = wid * 16 + (lane & 15);
    const uint32_t aoff = (uint32_t)arow * 128;
    const uint32_t axr  = (uint32_t)(arow & 7) * 16;
    const int ka = (lane >> 4) * 16;
    const int nrow_b = ((lane >> 4) & 1) * 8 + (lane & 7);
    const int kb = ((lane >> 3) & 1) * 16;
    const int vm = lane >> 3;
    const int vrow_b = (vm & 1) * 8 + (lane & 7);
    const int vcol_b = (vm >> 1) * 16;

    uint32_t qf[4][4];
    float accO[8][4];
#pragma unroll
    for (int nt = 0; nt < 8; nt++)
#pragma unroll
        for (int e = 0; e < 4; e++) accO[nt][e] = 0.0f;
    float m2[2] = {-3.0e38f, -3.0e38f};
    float lsum[2] = {0.0f, 0.0f};

    const int mrow = lane >> 2;
    const int cb = (lane & 3) * 2;
    const int irow0 = i0 + wid * 16 + mrow;
    const int irow1 = irow0 + 8;

    for (int jt = 0; jt < NJ; jt++) {
        if (jt + 1 < NJ) {
            const uint32_t st = tb + F_KV0 + ((jt + 1) & 1) * F_STG;
            const size_t kgj = kg + (size_t)(jt + 1) * 128 * strKV;
#pragma unroll
            for (int i = 0; i < 4; i++) {
                CP16(st + so[i],       Kp + kgj + i * 8);
                CP16(st + F_V + so[i], Vp + kgj + i * 8);
            }
            CP_COMMIT();
            CP_WAIT1();
        } else {
            CP_WAIT0();
        }
        __syncthreads();

        if (jt == 0) {
#pragma unroll
            for (int ks = 0; ks < 4; ks++)
                LDSM4(qf[ks], tb + aoff + (((uint32_t)(ks * 32 + ka)) ^ axr));
        }
        const uint32_t sb = tb + F_KV0 + (jt & 1) * F_STG;

        float accS[16][4];
#pragma unroll
        for (int nt = 0; nt < 16; nt++)
#pragma unroll
            for (int e = 0; e < 4; e++) accS[nt][e] = 0.0f;

#pragma unroll
        for (int ks = 0; ks < 4; ks++) {
            const uint32_t cbb = (uint32_t)(ks * 32 + kb);
#pragma unroll
            for (int ntp = 0; ntp < 8; ntp++) {
                const int r = ntp * 16 + nrow_b;
                uint32_t bf4[4];
                LDSM4(bf4, sb + (uint32_t)r * 128 + (cbb ^ ((uint32_t)(r & 7) * 16)));
                MMAH(accS[2 * ntp],     qf[ks], bf4[0], bf4[1]);
                MMAH(accS[2 * ntp + 1], qf[ks], bf4[2], bf4[3]);
            }
        }

        const int j0 = jt * 128;
        const bool maskTile = causal && (jt == NJ - 1);
#pragma unroll
        for (int nt = 0; nt < 16; nt++)
#pragma unroll
            for (int e = 0; e < 4; e++) accS[nt][e] *= cfg::SC2;
        if (maskTile) {
#pragma unroll
            for (int nt = 0; nt < 16; nt++) {
                const int jc = j0 + nt * 8 + cb;
                if (jc     > irow0) accS[nt][0] = -3.0e38f;
                if (jc + 1 > irow0) accS[nt][1] = -3.0e38f;
                if (jc     > irow1) accS[nt][2] = -3.0e38f;
                if (jc + 1 > irow1) accS[nt][3] = -3.0e38f;
            }
        }

        float mx0 = -3.0e38f, mx1 = -3.0e38f;
#pragma unroll
        for (int nt = 0; nt < 16; nt++) {
            mx0 = fmaxf(mx0, fmaxf(accS[nt][0], accS[nt][1]));
            mx1 = fmaxf(mx1, fmaxf(accS[nt][2], accS[nt][3]));
        }
        mx0 = fmaxf(mx0, __shfl_xor_sync(0xffffffffu, mx0, 1));
        mx0 = fmaxf(mx0, __shfl_xor_sync(0xffffffffu, mx0, 2));
        mx1 = fmaxf(mx1, __shfl_xor_sync(0xffffffffu, mx1, 1));
        mx1 = fmaxf(mx1, __shfl_xor_sync(0xffffffffu, mx1, 2));
        const float mn0 = fmaxf(m2[0], mx0);
        const float mn1 = fmaxf(m2[1], mx1);
        const float al0 = exp2f(m2[0] - mn0);
        const float al1 = exp2f(m2[1] - mn1);
        m2[0] = mn0; m2[1] = mn1;

        float s0 = 0.0f, s1 = 0.0f;
#pragma unroll
        for (int nt = 0; nt < 16; nt++) {
            float p0 = exp2f(accS[nt][0] - mn0);
            float p1 = exp2f(accS[nt][1] - mn0);
            float p2 = exp2f(accS[nt][2] - mn1);
            float p3 = exp2f(accS[nt][3] - mn1);
            accS[nt][0] = p0; accS[nt][1] = p1;
            accS[nt][2] = p2; accS[nt][3] = p3;
            s0 += p0 + p1;
            s1 += p2 + p3;
        }
        s0 += __shfl_xor_sync(0xffffffffu, s0, 1);
        s0 += __shfl_xor_sync(0xffffffffu, s0, 2);
        s1 += __shfl_xor_sync(0xffffffffu, s1, 1);
        s1 += __shfl_xor_sync(0xffffffffu, s1, 2);
        lsum[0] = lsum[0] * al0 + s0;
        lsum[1] = lsum[1] * al1 + s1;

#pragma unroll
        for (int nt = 0; nt < 8; nt++) {
            accO[nt][0] *= al0; accO[nt][1] *= al0;
            accO[nt][2] *= al1; accO[nt][3] *= al1;
        }

#pragma unroll
        for (int ks = 0; ks < 8; ks++) {
            uint32_t ph[4];
#pragma unroll
            for (int q = 0; q < 2; q++) {
                ph[2 * q]     = packh2(accS[2 * ks + q][0], accS[2 * ks + q][1]);
                ph[2 * q + 1] = packh2(accS[2 * ks + q][2], accS[2 * ks + q][3]);
            }
            const int jr = ks * 16 + vrow_b;
            const uint32_t roff = (uint32_t)jr * 128;
            const uint32_t xr = (uint32_t)(jr & 7) * 16;
#pragma unroll
            for (int ntp = 0; ntp < 4; ntp++) {
                uint32_t vf4[4];
                LDSM4T(vf4, sb + F_V + roff + (((uint32_t)(ntp * 32 + vcol_b)) ^ xr));
                MMAH(accO[2 * ntp],     ph, vf4[0], vf4[1]);
                MMAH(accO[2 * ntp + 1], ph, vf4[2], vf4[3]);
            }
        }
        __syncthreads();
    }

    const float li0 = 1.0f / lsum[0];
    const float li1 = 1.0f / lsum[1];
#pragma unroll
    for (int nt = 0; nt < 8; nt++) {
        const int d = h * cfg::HD + nt * 8 + cb;
        const size_t o0 = (size_t)(b * Tq + irow0) * cfg::E + d;
        const size_t o1 = (size_t)(b * Tq + irow1) * cfg::E + d;
        *(uint32_t*)(Oh + o0) = packh2(accO[nt][0] * li0, accO[nt][1] * li0);
        *(uint32_t*)(Oh + o1) = packh2(accO[nt][2] * li1, accO[nt][3] * li1);
    }
}

// ---------------------------------------------------------------------------
// LayerNorm -> fp16
// ---------------------------------------------------------------------------
__global__ void ln_h(const float* __restrict__ X, const float* __restrict__ gam,
                     const float* __restrict__ bet, uint16_t* __restrict__ H) {
    __shared__ float red[256];
    const int row = blockIdx.x;
    const int tid = threadIdx.x;
    const float4 v = ((const float4*)(X + (size_t)row * cfg::E))[tid];

    float s = v.x + v.y + v.z + v.w;
    red[tid] = s; __syncthreads();
    for (int off = 128; off; off >>= 1) {
        if (tid < off) red[tid] += red[tid + off];
        __syncthreads();
    }
    const float mu = red[0] * (1.0f / cfg::E);
    __syncthreads();

    const float dx = v.x - mu, dy = v.y - mu, dz = v.z - mu, dw = v.w - mu;
    red[tid] = dx*dx + dy*dy + dz*dz + dw*dw; __syncthreads();
    for (int off = 128; off; off >>= 1) {
        if (tid < off) red[tid] += red[tid + off];
        __syncthreads();
    }
    const float var = red[0] * (1.0f / cfg::E);
    const float r = rsqrtf(var + 1e-5f);

    const float4 g4 = ((const float4*)gam)[tid];
    const float4 b4 = ((const float4*)bet)[tid];
    ushort4 o;
    o.x = h16(dx * r * g4.x + b4.x);
    o.y = h16(dy * r * g4.y + b4.y);
    o.z = h16(dz * r * g4.z + b4.z);
    o.w = h16(dw * r * g4.w + b4.w);
    ((ushort4*)(H + (size_t)row * cfg::E))[tid] = o;
}

__global__ void split_h(const float* __restrict__ X, uint16_t* __restrict__ H, int n4) {
    const int i = blockIdx.x * 256 + threadIdx.x;
    if (i >= n4) return;
    const float4 v = ((const float4*)X)[i];
    ushort4 o;
    o.x = h16(v.x); o.y = h16(v.y); o.z = h16(v.z); o.w = h16(v.w);
    ((ushort4*)H)[i] = o;
}

// W[K,N] fp32 -> [N,K] fp16
__global__ void transpose_h(const float* __restrict__ W, uint16_t* __restrict__ H,
                            int Kd, int Nd) {
    __shared__ float tile[32][33];
    const int n0 = blockIdx.x * 32, k0 = blockIdx.y * 32;
    const int tx = threadIdx.x, ty = threadIdx.y;
    for (int r = ty; r < 32; r += 8)
        tile[r][tx] = W[(size_t)(k0 + r) * Nd + n0 + tx];
    __syncthreads();
    for (int r = ty; r < 32; r += 8)
        H[(size_t)(n0 + r) * Kd + k0 + tx] = h16(tile[tx][r]);
}

// ---------------------------------------------------------------------------
// Launch sequence
// ---------------------------------------------------------------------------
extern "C" void kernel_launch(void* const* d_in, const int* in_sizes, int n_in,
                              void* d_out, int out_size) {
    using namespace cfg;
    const float* x        = (const float*)d_in[0];
    const float* context  = (const float*)d_in[1];
    const float* ln1_g    = (const float*)d_in[2];
    const float* ln1_b    = (const float*)d_in[3];
    const float* ln2_g    = (const float*)d_in[4];
    const float* ln2_b    = (const float*)d_in[5];
    const float* ln3_g    = (const float*)d_in[6];
    const float* ln3_b    = (const float*)d_in[7];
    const float* Wq_s     = (const float*)d_in[8];
    const float* Wk_s     = (const float*)d_in[9];
    const float* Wv_s     = (const float*)d_in[10];
    const float* proj_s_w = (const float*)d_in[11];
    const float* proj_s_b = (const float*)d_in[12];
    const float* Wq_c     = (const float*)d_in[13];
    const float* Wk_c     = (const float*)d_in[14];
    const float* Wv_c     = (const float*)d_in[15];
    const float* proj_c_w = (const float*)d_in[16];
    const float* proj_c_b = (const float*)d_in[17];
    const float* w1       = (const float*)d_in[18];
    const float* b1       = (const float*)d_in[19];
    const float* w2       = (const float*)d_in[20];
    const float* b2       = (const float*)d_in[21];
    float* out = (float*)d_out;

    float *px1, *px2;
    uint16_t *ah, *ch, *bh, *qh, *fh;
    cudaGetSymbolAddress((void**)&px1, g_x1);
    cudaGetSymbolAddress((void**)&px2, g_x2);
    cudaGetSymbolAddress((void**)&ah, g_a);
    cudaGetSymbolAddress((void**)&ch, g_c);
    cudaGetSymbolAddress((void**)&bh, g_b);
    cudaGetSymbolAddress((void**)&qh, g_q);
    cudaGetSymbolAddress((void**)&fh, g_f);

    const int GEMM_SMEM = 2 * H_STAGE + 1024;
    cudaFuncSetAttribute(hgemm,   cudaFuncAttributeMaxDynamicSharedMemorySize, GEMM_SMEM);
    cudaFuncSetAttribute(flash_h, cudaFuncAttributeMaxDynamicSharedMemorySize, FLASH_SMEM);

    const int M = B * T;
    const dim3 gE   (E / 128,     M / 128);
    const dim3 gQKV (3 * E / 128, M / 128);
    const dim3 gKV  (2 * E / 128, M / 128);
    const dim3 g4E  (4 * E / 128, M / 128);
    const dim3 gfl  (T / 128, BH);
    const int nME4 = (M * E) / 4;
    const dim3 gtEE (E / 32, E / 32);
    const dim3 gtE4 (4 * E / 32, E / 32);
    const dim3 gt4E (E / 32, 4 * E / 32);
    const dim3 tbt(32, 8);

    // ---- self attention (causal): merged QKV ----
    ln_h<<<M, 256>>>(x, ln1_g, ln1_b, ah);
    transpose_h<<<gtEE, tbt>>>(Wq_s, bh,                   E, E);
    transpose_h<<<gtEE, tbt>>>(Wk_s, bh + (size_t)E * E,   E, E);
    transpose_h<<<gtEE, tbt>>>(Wv_s, bh + (size_t)2*E*E,   E, E);
    hgemm<<<gQKV, 256, GEMM_SMEM>>>(ah, bh, nullptr, nullptr,
                                    nullptr, fh, 3 * E, E, 0);
    flash_h<<<gfl, 256, FLASH_SMEM>>>(fh, fh + E, fh + 2 * E, qh, T, S, 3 * E, 3 * E, 1);
    transpose_h<<<gtEE, tbt>>>(proj_s_w, bh, E, E);
    hgemm<<<gE, 256, GEMM_SMEM>>>(qh, bh, proj_s_b, x, px1, nullptr, E, E, 0);

    // ---- cross attention (context NOT normalized) ----
    ln_h<<<M, 256>>>(px1, ln2_g, ln2_b, ah);
    transpose_h<<<gtEE, tbt>>>(Wq_c, bh, E, E);
    hgemm<<<gE, 256, GEMM_SMEM>>>(ah, bh, nullptr, nullptr, nullptr, qh, E, E, 0);
    split_h<<<(nME4 + 255) / 256, 256>>>(context, ch, nME4);
    transpose_h<<<gtEE, tbt>>>(Wk_c, bh,                 E, E);
    transpose_h<<<gtEE, tbt>>>(Wv_c, bh + (size_t)E * E, E, E);
    hgemm<<<gKV, 256, GEMM_SMEM>>>(ch, bh, nullptr, nullptr, nullptr, fh, 2 * E, E, 0);
    flash_h<<<gfl, 256, FLASH_SMEM>>>(qh, fh, fh + E, ah, T, S, E, 2 * E, 0);
    transpose_h<<<gtEE, tbt>>>(proj_c_w, bh, E, E);
    hgemm<<<gE, 256, GEMM_SMEM>>>(ah, bh, proj_c_b, px1, px2, nullptr, E, E, 0);

    // ---- FFN ----
    ln_h<<<M, 256>>>(px2, ln3_g, ln3_b, qh);
    transpose_h<<<gtE4, tbt>>>(w1, bh, E, 4 * E);
    hgemm<<<g4E, 256, GEMM_SMEM>>>(qh, bh, b1, nullptr, nullptr, fh, 4 * E, E, 1);
    transpose_h<<<gt4E, tbt>>>(w2, bh, 4 * E, E);
    hgemm<<<gE, 256, GEMM_SMEM>>>(fh, bh, b2, px2, out, nullptr, E, 4 * E, 0);
}

// round 9
// speedup vs baseline: 6.4484x; 1.0192x over previous
#include <cuda_runtime.h>
#include <cuda_bf16.h>
#include <cuda_fp16.h>
#include <math.h>
#include <stdint.h>

// ---------------------------------------------------------------------------
// DecoderLayerWithContext — Round 9
// vs R8 (989us): (1) single weight-prep kernel for all 10 transposes,
// (2) hgemm: 3-stage cp.async ring + single syncthreads per K-chunk,
// (3) flash: same 3-stage restructure. fp16 everywhere (validated R8).
// ---------------------------------------------------------------------------

namespace cfg {
constexpr int E  = 1024;
constexpr int NH = 16;
constexpr int HD = 64;
constexpr int B  = 2;
constexpr int T  = 2048;
constexpr int S  = 2048;
constexpr int BH = B * NH;
constexpr float SC2 = 0.03125f * 1.44269504f;   // (1/sqrt(E)) * log2(e)
}

// -------------------------- device scratch ---------------------------------
__device__ float    g_x1[cfg::B * cfg::T * cfg::E];
__device__ float    g_x2[cfg::B * cfg::T * cfg::E];
__device__ uint16_t g_a [(size_t)4  * 1024 * 1024];   // ln/flash-out fp16
__device__ uint16_t g_c [(size_t)4  * 1024 * 1024];   // context fp16
__device__ uint16_t g_q [(size_t)4  * 1024 * 1024];   // q / ln3 / flash-out swap
__device__ uint16_t g_f [(size_t)16 * 1024 * 1024];   // wide intermediate fp16
__device__ uint16_t g_w [(size_t)16 * 1024 * 1024];   // ALL transposed weights fp16

// g_w layout (units of 1M = E*E halves):
// 0:Wq_s 1:Wk_s 2:Wv_s 3:proj_s 4:Wq_c 5:Wk_c 6:Wv_c 7:proj_c 8..11:w1 12..15:w2
constexpr size_t WU = (size_t)1024 * 1024;

// -------------------------- asm helpers ------------------------------------
__device__ __forceinline__ uint32_t smem_u32(const void* p) {
    uint32_t a;
    asm("{ .reg .u64 t; cvta.to.shared.u64 t, %1; cvt.u32.u64 %0, t; }" : "=r"(a) : "l"(p));
    return a;
}
#define CP16(s, g) \
    asm volatile("cp.async.cg.shared.global [%0], [%1], 16;" :: "r"(s), "l"(g))
#define CP_COMMIT()  asm volatile("cp.async.commit_group;" ::: "memory")
#define CP_WAIT0()   asm volatile("cp.async.wait_group 0;" ::: "memory")
#define CP_WAIT1()   asm volatile("cp.async.wait_group 1;" ::: "memory")

#define LDSM4(r, addr)                                                        \
    asm volatile("ldmatrix.sync.aligned.m8n8.x4.shared.b16 {%0,%1,%2,%3}, [%4];" \
        : "=r"((r)[0]), "=r"((r)[1]), "=r"((r)[2]), "=r"((r)[3]) : "r"(addr))
#define LDSM4T(r, addr)                                                       \
    asm volatile("ldmatrix.sync.aligned.m8n8.x4.trans.shared.b16 {%0,%1,%2,%3}, [%4];" \
        : "=r"((r)[0]), "=r"((r)[1]), "=r"((r)[2]), "=r"((r)[3]) : "r"(addr))

#define MMAH(d, a, b0, b1)                                                    \
    asm("mma.sync.aligned.m16n8k16.row.col.f32.f16.f16.f32 "                  \
        "{%0,%1,%2,%3},{%4,%5,%6,%7},{%8,%9},{%0,%1,%2,%3};"                  \
        : "+f"((d)[0]), "+f"((d)[1]), "+f"((d)[2]), "+f"((d)[3])              \
        : "r"((a)[0]), "r"((a)[1]), "r"((a)[2]), "r"((a)[3]), "r"(b0), "r"(b1))

__device__ __forceinline__ uint32_t packh2(float lo, float hi) {
    __half2 h = __floats2half2_rn(lo, hi);
    return *reinterpret_cast<uint32_t*>(&h);
}
__device__ __forceinline__ unsigned short h16(float x) {
    __half h = __float2half_rn(x);
    return *reinterpret_cast<unsigned short*>(&h);
}
__device__ __forceinline__ float gelu_f(float x) {
    return 0.5f * x * (1.0f + erff(x * 0.7071067811865475f));
}

// ---------------------------------------------------------------------------
// fp16 HMMA GEMM: C[M,N] = epi(A[M,K] * B[N,K]^T)
// 128x128 tile, K chunks of 64, 3-stage cp.async ring, ONE sync per chunk.
// ---------------------------------------------------------------------------
constexpr int H_OFF_B = 16384;
constexpr int H_STAGE = 32768;
constexpr int GEMM_SMEM = 3 * H_STAGE + 1024;

__global__ void __launch_bounds__(256, 2)
hgemm(const uint16_t* __restrict__ A, const uint16_t* __restrict__ Bm,
      const float* __restrict__ bias, const float* __restrict__ res,
      float* __restrict__ C, uint16_t* __restrict__ Ch,
      int N, int K, int do_gelu) {
    extern __shared__ uint8_t dsm[];
    uint8_t* tiles = (uint8_t*)(((uintptr_t)dsm + 1023) & ~(uintptr_t)1023);
    const uint32_t tb = smem_u32(tiles);

    const int tid  = threadIdx.x;
    const int lane = tid & 31;
    const int wid  = tid >> 5;
    const int wr   = wid >> 2;
    const int wc   = wid & 3;
    const int row0 = blockIdx.y * 128;
    const int col0 = blockIdx.x * 128;

    const int lrow = tid >> 1, lhalf = tid & 1;
    uint32_t so[4];
#pragma unroll
    for (int i = 0; i < 4; i++) {
        uint32_t o = (uint32_t)lrow * 128 + (uint32_t)lhalf * 64 + i * 16;
        so[i] = o ^ ((o >> 3) & 0x70);
    }
    const size_t a_base = (size_t)(row0 + lrow) * K + lhalf * 32;
    const size_t b_base = (size_t)(col0 + lrow) * K + lhalf * 32;

    const int ka = (lane >> 4) * 16;
    const int kb = ((lane >> 3) & 1) * 16;
    uint32_t aoff[4], xA[4];
#pragma unroll
    for (int mt = 0; mt < 4; mt++) {
        int r = wr * 64 + mt * 16 + (lane & 15);
        aoff[mt] = (uint32_t)r * 128;
        xA[mt] = (uint32_t)(r & 7) * 16;
    }
    uint32_t boff[2], xB[2];
#pragma unroll
    for (int p = 0; p < 2; p++) {
        int r = wc * 32 + p * 16 + ((lane >> 4) & 1) * 8 + (lane & 7);
        boff[p] = (uint32_t)r * 128;
        xB[p] = (uint32_t)(r & 7) * 16;
    }

    float acc[4][4][4];
#pragma unroll
    for (int mt = 0; mt < 4; mt++)
#pragma unroll
        for (int nt = 0; nt < 4; nt++)
#pragma unroll
            for (int e = 0; e < 4; e++) acc[mt][nt][e] = 0.0f;

    const int NC = K >> 6;
    // prologue: chunks 0 and 1 into stages 0,1
#pragma unroll
    for (int pc = 0; pc < 2; pc++) {
        if (pc < NC) {
            const uint32_t st = tb + pc * H_STAGE;
            const int kc = pc << 6;
#pragma unroll
            for (int i = 0; i < 4; i++) {
                CP16(st + so[i],           A  + a_base + kc + i * 8);
                CP16(st + H_OFF_B + so[i], Bm + b_base + kc + i * 8);
            }
            CP_COMMIT();
        }
    }

    int stage = 0;
    for (int c = 0; c < NC; c++) {
        if (c + 1 < NC) CP_WAIT1(); else CP_WAIT0();
        __syncthreads();   // stage c ready for all; frees stage (c+2)%3 target

        if (c + 2 < NC) {
            int pst = stage + 2; if (pst >= 3) pst -= 3;
            const uint32_t st = tb + pst * H_STAGE;
            const int kc = (c + 2) << 6;
#pragma unroll
            for (int i = 0; i < 4; i++) {
                CP16(st + so[i],           A  + a_base + kc + i * 8);
                CP16(st + H_OFF_B + so[i], Bm + b_base + kc + i * 8);
            }
            CP_COMMIT();
        }

        const uint32_t sb = tb + stage * H_STAGE;
#pragma unroll
        for (int ks = 0; ks < 4; ks++) {
            uint32_t ah[4][4], bh[2][4];
            const uint32_t cba = (uint32_t)(ks * 32 + ka);
#pragma unroll
            for (int mt = 0; mt < 4; mt++)
                LDSM4(ah[mt], sb + aoff[mt] + (cba ^ xA[mt]));
            const uint32_t cbb = (uint32_t)(ks * 32 + kb);
#pragma unroll
            for (int p = 0; p < 2; p++)
                LDSM4(bh[p], sb + H_OFF_B + boff[p] + (cbb ^ xB[p]));
#pragma unroll
            for (int mt = 0; mt < 4; mt++)
#pragma unroll
                for (int nt = 0; nt < 4; nt++) {
                    const int p = nt >> 1, q = (nt & 1) * 2;
                    MMAH(acc[mt][nt], ah[mt], bh[p][q], bh[p][q + 1]);
                }
        }
        if (++stage == 3) stage = 0;
    }

    const int mrow = lane >> 2;
    const int ncol = (lane & 3) * 2;
#pragma unroll
    for (int mt = 0; mt < 4; mt++) {
#pragma unroll
        for (int half = 0; half < 2; half++) {
            const int r = row0 + wr * 64 + mt * 16 + mrow + half * 8;
#pragma unroll
            for (int nt = 0; nt < 4; nt++) {
                float v0 = acc[mt][nt][half * 2 + 0];
                float v1 = acc[mt][nt][half * 2 + 1];
                const int cc = col0 + wc * 32 + nt * 8 + ncol;
                if (bias) { v0 += bias[cc]; v1 += bias[cc + 1]; }
                if (do_gelu) { v0 = gelu_f(v0); v1 = gelu_f(v1); }
                if (res) {
                    v0 += res[(size_t)r * N + cc];
                    v1 += res[(size_t)r * N + cc + 1];
                }
                if (C) *(float2*)(C + (size_t)r * N + cc) = make_float2(v0, v1);
                if (Ch) *(uint32_t*)(Ch + (size_t)r * N + cc) = packh2(v0, v1);
            }
        }
    }
}

// ---------------------------------------------------------------------------
// Fused flash attention, fp16, 3-stage KV ring, one sync per j-tile.
// ---------------------------------------------------------------------------
constexpr int F_KV0 = 16384;
constexpr int F_V   = 16384;
constexpr int F_STG = 32768;
constexpr int FLASH_SMEM = 16384 + 3 * F_STG + 1024;

__global__ void __launch_bounds__(256, 1)
flash_h(const uint16_t* __restrict__ Q, const uint16_t* __restrict__ Kp,
        const uint16_t* __restrict__ Vp, uint16_t* __restrict__ Oh,
        int Tq, int Tk, int strQ, int strKV, int causal) {
    extern __shared__ uint8_t dsm[];
    uint8_t* basep = (uint8_t*)(((uintptr_t)dsm + 1023) & ~(uintptr_t)1023);
    const uint32_t tb = smem_u32(basep);

    const int bh = blockIdx.y;
    const int b = bh >> 4, h = bh & 15;
    int it = blockIdx.x;
    if (causal) it = (int)gridDim.x - 1 - it;
    const int i0 = it * 128;
    const int NJ = causal ? (it + 1) : (Tk >> 7);

    const int tid = threadIdx.x;
    const int lane = tid & 31;
    const int wid = tid >> 5;

    const int lrow = tid >> 1, lhalf = tid & 1;
    uint32_t so[4];
#pragma unroll
    for (int i = 0; i < 4; i++) {
        uint32_t o = (uint32_t)lrow * 128 + (uint32_t)lhalf * 64 + i * 16;
        so[i] = o ^ ((o >> 3) & 0x70);
    }
    const size_t qg = (size_t)(b * Tq + i0 + lrow) * strQ + h * cfg::HD + lhalf * 32;
    const size_t kg = (size_t)(b * Tk + lrow) * strKV + h * cfg::HD + lhalf * 32;

    // Q + KV stages 0,1
#pragma unroll
    for (int i = 0; i < 4; i++) CP16(tb + so[i], Q + qg + i * 8);
    {
        const uint32_t st = tb + F_KV0;
#pragma unroll
        for (int i = 0; i < 4; i++) {
            CP16(st + so[i],       Kp + kg + i * 8);
            CP16(st + F_V + so[i], Vp + kg + i * 8);
        }
        CP_COMMIT();
    }
    if (1 < NJ) {
        const uint32_t st = tb + F_KV0 + F_STG;
        const size_t kg1 = kg + (size_t)128 * strKV;
#pragma unroll
        for (int i = 0; i < 4; i++) {
            CP16(st + so[i],       Kp + kg1 + i * 8);
            CP16(st + F_V + so[i], Vp + kg1 + i * 8);
        }
        CP_COMMIT();
    }

    const int arow = wid * 16 + (lane & 15);
    const uint32_t aoff = (uint32_t)arow * 128;
    const uint32_t axr  = (uint32_t)(arow & 7) * 16;
    const int ka = (lane >> 4) * 16;
    const int nrow_b = ((lane >> 4) & 1) * 8 + (lane & 7);
    const int kb = ((lane >> 3) & 1) * 16;
    const int vm = lane >> 3;
    const int vrow_b = (vm & 1) * 8 + (lane & 7);
    const int vcol_b = (vm >> 1) * 16;

    uint32_t qf[4][4];
    float accO[8][4];
#pragma unroll
    for (int nt = 0; nt < 8; nt++)
#pragma unroll
        for (int e = 0; e < 4; e++) accO[nt][e] = 0.0f;
    float m2[2] = {-3.0e38f, -3.0e38f};
    float lsum[2] = {0.0f, 0.0f};

    const int mrow = lane >> 2;
    const int cb = (lane & 3) * 2;
    const int irow0 = i0 + wid * 16 + mrow;
    const int irow1 = irow0 + 8;

    int stage = 0;
    for (int jt = 0; jt < NJ; jt++) {
        if (jt + 1 < NJ) CP_WAIT1(); else CP_WAIT0();
        __syncthreads();

        if (jt + 2 < NJ) {
            int pst = stage + 2; if (pst >= 3) pst -= 3;
            const uint32_t st = tb + F_KV0 + pst * F_STG;
            const size_t kgj = kg + (size_t)(jt + 2) * 128 * strKV;
#pragma unroll
            for (int i = 0; i < 4; i++) {
                CP16(st + so[i],       Kp + kgj + i * 8);
                CP16(st + F_V + so[i], Vp + kgj + i * 8);
            }
            CP_COMMIT();
        }

        if (jt == 0) {
#pragma unroll
            for (int ks = 0; ks < 4; ks++)
                LDSM4(qf[ks], tb + aoff + (((uint32_t)(ks * 32 + ka)) ^ axr));
        }
        const uint32_t sb = tb + F_KV0 + stage * F_STG;

        float accS[16][4];
#pragma unroll
        for (int nt = 0; nt < 16; nt++)
#pragma unroll
            for (int e = 0; e < 4; e++) accS[nt][e] = 0.0f;

#pragma unroll
        for (int ks = 0; ks < 4; ks++) {
            const uint32_t cbb = (uint32_t)(ks * 32 + kb);
#pragma unroll
            for (int ntp = 0; ntp < 8; ntp++) {
                const int r = ntp * 16 + nrow_b;
                uint32_t bf4[4];
                LDSM4(bf4, sb + (uint32_t)r * 128 + (cbb ^ ((uint32_t)(r & 7) * 16)));
                MMAH(accS[2 * ntp],     qf[ks], bf4[0], bf4[1]);
                MMAH(accS[2 * ntp + 1], qf[ks], bf4[2], bf4[3]);
            }
        }

        const int j0 = jt * 128;
        const bool maskTile = causal && (jt == NJ - 1);
#pragma unroll
        for (int nt = 0; nt < 16; nt++)
#pragma unroll
            for (int e = 0; e < 4; e++) accS[nt][e] *= cfg::SC2;
        if (maskTile) {
#pragma unroll
            for (int nt = 0; nt < 16; nt++) {
                const int jc = j0 + nt * 8 + cb;
                if (jc     > irow0) accS[nt][0] = -3.0e38f;
                if (jc + 1 > irow0) accS[nt][1] = -3.0e38f;
                if (jc     > irow1) accS[nt][2] = -3.0e38f;
                if (jc + 1 > irow1) accS[nt][3] = -3.0e38f;
            }
        }

        float mx0 = -3.0e38f, mx1 = -3.0e38f;
#pragma unroll
        for (int nt = 0; nt < 16; nt++) {
            mx0 = fmaxf(mx0, fmaxf(accS[nt][0], accS[nt][1]));
            mx1 = fmaxf(mx1, fmaxf(accS[nt][2], accS[nt][3]));
        }
        mx0 = fmaxf(mx0, __shfl_xor_sync(0xffffffffu, mx0, 1));
        mx0 = fmaxf(mx0, __shfl_xor_sync(0xffffffffu, mx0, 2));
        mx1 = fmaxf(mx1, __shfl_xor_sync(0xffffffffu, mx1, 1));
        mx1 = fmaxf(mx1, __shfl_xor_sync(0xffffffffu, mx1, 2));
        const float mn0 = fmaxf(m2[0], mx0);
        const float mn1 = fmaxf(m2[1], mx1);
        const float al0 = exp2f(m2[0] - mn0);
        const float al1 = exp2f(m2[1] - mn1);
        m2[0] = mn0; m2[1] = mn1;

        float s0 = 0.0f, s1 = 0.0f;
#pragma unroll
        for (int nt = 0; nt < 16; nt++) {
            float p0 = exp2f(accS[nt][0] - mn0);
            float p1 = exp2f(accS[nt][1] - mn0);
            float p2 = exp2f(accS[nt][2] - mn1);
            float p3 = exp2f(accS[nt][3] - mn1);
            accS[nt][0] = p0; accS[nt][1] = p1;
            accS[nt][2] = p2; accS[nt][3] = p3;
            s0 += p0 + p1;
            s1 += p2 + p3;
        }
        s0 += __shfl_xor_sync(0xffffffffu, s0, 1);
        s0 += __shfl_xor_sync(0xffffffffu, s0, 2);
        s1 += __shfl_xor_sync(0xffffffffu, s1, 1);
        s1 += __shfl_xor_sync(0xffffffffu, s1, 2);
        lsum[0] = lsum[0] * al0 + s0;
        lsum[1] = lsum[1] * al1 + s1;

#pragma unroll
        for (int nt = 0; nt < 8; nt++) {
            accO[nt][0] *= al0; accO[nt][1] *= al0;
            accO[nt][2] *= al1; accO[nt][3] *= al1;
        }

#pragma unroll
        for (int ks = 0; ks < 8; ks++) {
            uint32_t ph[4];
#pragma unroll
            for (int q = 0; q < 2; q++) {
                ph[2 * q]     = packh2(accS[2 * ks + q][0], accS[2 * ks + q][1]);
                ph[2 * q + 1] = packh2(accS[2 * ks + q][2], accS[2 * ks + q][3]);
            }
            const int jr = ks * 16 + vrow_b;
            const uint32_t roff = (uint32_t)jr * 128;
            const uint32_t xr = (uint32_t)(jr & 7) * 16;
#pragma unroll
            for (int ntp = 0; ntp < 4; ntp++) {
                uint32_t vf4[4];
                LDSM4T(vf4, sb + F_V + roff + (((uint32_t)(ntp * 32 + vcol_b)) ^ xr));
                MMAH(accO[2 * ntp],     ph, vf4[0], vf4[1]);
                MMAH(accO[2 * ntp + 1], ph, vf4[2], vf4[3]);
            }
        }
        if (++stage == 3) stage = 0;
    }

    const float li0 = 1.0f / lsum[0];
    const float li1 = 1.0f / lsum[1];
#pragma unroll
    for (int nt = 0; nt < 8; nt++) {
        const int d = h * cfg::HD + nt * 8 + cb;
        const size_t o0 = (size_t)(b * Tq + irow0) * cfg::E + d;
        const size_t o1 = (size_t)(b * Tq + irow1) * cfg::E + d;
        *(uint32_t*)(Oh + o0) = packh2(accO[nt][0] * li0, accO[nt][1] * li0);
        *(uint32_t*)(Oh + o1) = packh2(accO[nt][2] * li1, accO[nt][3] * li1);
    }
}

// ---------------------------------------------------------------------------
// Weight prep: ALL transposes (fp32 [K,N] -> fp16 [N,K]) in ONE launch.
// Flat tile ids: [0,8192) = eight ExE weights; [8192,12288) = w1; rest = w2.
// ---------------------------------------------------------------------------
__global__ void prep_weights(
    const float* __restrict__ Wq_s, const float* __restrict__ Wk_s,
    const float* __restrict__ Wv_s, const float* __restrict__ proj_s,
    const float* __restrict__ Wq_c, const float* __restrict__ Wk_c,
    const float* __restrict__ Wv_c, const float* __restrict__ proj_c,
    const float* __restrict__ w1,   const float* __restrict__ w2,
    uint16_t* __restrict__ Wdst) {
    __shared__ float tile[32][33];
    const int id = blockIdx.x;
    const float* W;
    uint16_t* H;
    int n0, k0, Kd, Nd;
    if (id < 8192) {
        const int w = id >> 10, t = id & 1023;
        const float* srcs[8] = {Wq_s, Wk_s, Wv_s, proj_s, Wq_c, Wk_c, Wv_c, proj_c};
        W = srcs[w];
        H = Wdst + (size_t)w * WU;
        n0 = (t & 31) * 32; k0 = (t >> 5) * 32;
        Kd = cfg::E; Nd = cfg::E;
    } else if (id < 12288) {
        const int t = id - 8192;                 // w1: [E,4E] -> [4E,E]
        W = w1; H = Wdst + 8 * WU;
        n0 = (t & 127) * 32; k0 = (t >> 7) * 32;
        Kd = cfg::E; Nd = 4 * cfg::E;
    } else {
        const int t = id - 12288;                // w2: [4E,E] -> [E,4E]
        W = w2; H = Wdst + 12 * WU;
        n0 = (t & 31) * 32; k0 = (t >> 5) * 32;
        Kd = 4 * cfg::E; Nd = cfg::E;
    }
    const int tx = threadIdx.x, ty = threadIdx.y;
    for (int r = ty; r < 32; r += 8)
        tile[r][tx] = W[(size_t)(k0 + r) * Nd + n0 + tx];
    __syncthreads();
    for (int r = ty; r < 32; r += 8)
        H[(size_t)(n0 + r) * Kd + k0 + tx] = h16(tile[tx][r]);
}

// ---------------------------------------------------------------------------
// LayerNorm -> fp16 ; fp32 -> fp16 copy
// ---------------------------------------------------------------------------
__global__ void ln_h(const float* __restrict__ X, const float* __restrict__ gam,
                     const float* __restrict__ bet, uint16_t* __restrict__ H) {
    __shared__ float red[256];
    const int row = blockIdx.x;
    const int tid = threadIdx.x;
    const float4 v = ((const float4*)(X + (size_t)row * cfg::E))[tid];

    float s = v.x + v.y + v.z + v.w;
    red[tid] = s; __syncthreads();
    for (int off = 128; off; off >>= 1) {
        if (tid < off) red[tid] += red[tid + off];
        __syncthreads();
    }
    const float mu = red[0] * (1.0f / cfg::E);
    __syncthreads();

    const float dx = v.x - mu, dy = v.y - mu, dz = v.z - mu, dw = v.w - mu;
    red[tid] = dx*dx + dy*dy + dz*dz + dw*dw; __syncthreads();
    for (int off = 128; off; off >>= 1) {
        if (tid < off) red[tid] += red[tid + off];
        __syncthreads();
    }
    const float var = red[0] * (1.0f / cfg::E);
    const float r = rsqrtf(var + 1e-5f);

    const float4 g4 = ((const float4*)gam)[tid];
    const float4 b4 = ((const float4*)bet)[tid];
    ushort4 o;
    o.x = h16(dx * r * g4.x + b4.x);
    o.y = h16(dy * r * g4.y + b4.y);
    o.z = h16(dz * r * g4.z + b4.z);
    o.w = h16(dw * r * g4.w + b4.w);
    ((ushort4*)(H + (size_t)row * cfg::E))[tid] = o;
}

__global__ void split_h(const float* __restrict__ X, uint16_t* __restrict__ H, int n4) {
    const int i = blockIdx.x * 256 + threadIdx.x;
    if (i >= n4) return;
    const float4 v = ((const float4*)X)[i];
    ushort4 o;
    o.x = h16(v.x); o.y = h16(v.y); o.z = h16(v.z); o.w = h16(v.w);
    ((ushort4*)H)[i] = o;
}

// ---------------------------------------------------------------------------
// Launch sequence
// ---------------------------------------------------------------------------
extern "C" void kernel_launch(void* const* d_in, const int* in_sizes, int n_in,
                              void* d_out, int out_size) {
    using namespace cfg;
    const float* x        = (const float*)d_in[0];
    const float* context  = (const float*)d_in[1];
    const float* ln1_g    = (const float*)d_in[2];
    const float* ln1_b    = (const float*)d_in[3];
    const float* ln2_g    = (const float*)d_in[4];
    const float* ln2_b    = (const float*)d_in[5];
    const float* ln3_g    = (const float*)d_in[6];
    const float* ln3_b    = (const float*)d_in[7];
    const float* Wq_s     = (const float*)d_in[8];
    const float* Wk_s     = (const float*)d_in[9];
    const float* Wv_s     = (const float*)d_in[10];
    const float* proj_s_w = (const float*)d_in[11];
    const float* proj_s_b = (const float*)d_in[12];
    const float* Wq_c     = (const float*)d_in[13];
    const float* Wk_c     = (const float*)d_in[14];
    const float* Wv_c     = (const float*)d_in[15];
    const float* proj_c_w = (const float*)d_in[16];
    const float* proj_c_b = (const float*)d_in[17];
    const float* w1       = (const float*)d_in[18];
    const float* b1       = (const float*)d_in[19];
    const float* w2       = (const float*)d_in[20];
    const float* b2       = (const float*)d_in[21];
    float* out = (float*)d_out;

    float *px1, *px2;
    uint16_t *ah, *ch, *qh, *fh, *wh;
    cudaGetSymbolAddress((void**)&px1, g_x1);
    cudaGetSymbolAddress((void**)&px2, g_x2);
    cudaGetSymbolAddress((void**)&ah, g_a);
    cudaGetSymbolAddress((void**)&ch, g_c);
    cudaGetSymbolAddress((void**)&qh, g_q);
    cudaGetSymbolAddress((void**)&fh, g_f);
    cudaGetSymbolAddress((void**)&wh, g_w);

    cudaFuncSetAttribute(hgemm,   cudaFuncAttributeMaxDynamicSharedMemorySize, GEMM_SMEM);
    cudaFuncSetAttribute(flash_h, cudaFuncAttributeMaxDynamicSharedMemorySize, FLASH_SMEM);

    const int M = B * T;
    const dim3 gE   (E / 128,     M / 128);
    const dim3 gQKV (3 * E / 128, M / 128);
    const dim3 gKV  (2 * E / 128, M / 128);
    const dim3 g4E  (4 * E / 128, M / 128);
    const dim3 gfl  (T / 128, BH);
    const int nME4 = (M * E) / 4;
    const dim3 tbt(32, 8);

    // ---- one-shot prep: all weights + context ----
    prep_weights<<<16384, tbt>>>(Wq_s, Wk_s, Wv_s, proj_s_w,
                                 Wq_c, Wk_c, Wv_c, proj_c_w, w1, w2, wh);
    split_h<<<(nME4 + 255) / 256, 256>>>(context, ch, nME4);

    // ---- self attention (causal): merged QKV (units 0,1,2 contiguous) ----
    ln_h<<<M, 256>>>(x, ln1_g, ln1_b, ah);
    hgemm<<<gQKV, 256, GEMM_SMEM>>>(ah, wh, nullptr, nullptr,
                                    nullptr, fh, 3 * E, E, 0);
    flash_h<<<gfl, 256, FLASH_SMEM>>>(fh, fh + E, fh + 2 * E, qh, T, S, 3 * E, 3 * E, 1);
    hgemm<<<gE, 256, GEMM_SMEM>>>(qh, wh + 3 * WU, proj_s_b, x, px1, nullptr, E, E, 0);

    // ---- cross attention (context NOT normalized): merged KV (units 5,6) ----
    ln_h<<<M, 256>>>(px1, ln2_g, ln2_b, ah);
    hgemm<<<gE, 256, GEMM_SMEM>>>(ah, wh + 4 * WU, nullptr, nullptr, nullptr, qh, E, E, 0);
    hgemm<<<gKV, 256, GEMM_SMEM>>>(ch, wh + 5 * WU, nullptr, nullptr, nullptr, fh, 2 * E, E, 0);
    flash_h<<<gfl, 256, FLASH_SMEM>>>(qh, fh, fh + E, ah, T, S, E, 2 * E, 0);
    hgemm<<<gE, 256, GEMM_SMEM>>>(ah, wh + 7 * WU, proj_c_b, px1, px2, nullptr, E, E, 0);

    // ---- FFN ----
    ln_h<<<M, 256>>>(px2, ln3_g, ln3_b, qh);
    hgemm<<<g4E, 256, GEMM_SMEM>>>(qh, wh + 8 * WU, b1, nullptr, nullptr, fh, 4 * E, E, 1);
    hgemm<<<gE, 256, GEMM_SMEM>>>(fh, wh + 12 * WU, b2, px2, out, nullptr, E, 4 * E, 0);
}